// round 2
// baseline (speedup 1.0000x reference)
#include <cuda_runtime.h>

// Problem constants
#define BB 4
#define TT 2048
#define CC 1024
#define HH 16
#define DH 64
#define MM (BB*TT)          // 8192 rows for both GEMMs

// Scratch (device globals — no allocation allowed)
__device__ float g_Q[BB*HH*TT*DH];   // [B,H,T,D]
__device__ float g_K[BB*HH*TT*DH];
__device__ float g_V[BB*HH*TT*DH];
__device__ float g_Y[BB*TT*CC];      // attention output, [B,T,C]

// ---------------------------------------------------------------------------
// 128x128x16 register-blocked SGEMM. MODE 0: QKV (scatter epilogue into
// g_Q/g_K/g_V with [B,H,T,D] layout). MODE 1: proj (A = g_Y, write out).
// ---------------------------------------------------------------------------
template<int MODE>
__global__ __launch_bounds__(256) void sgemm_kernel(const float* __restrict__ A,
                                                    const float* __restrict__ W,
                                                    const float* __restrict__ bias,
                                                    float* __restrict__ out,
                                                    int N)
{
    const int K = CC;
    __shared__ float As[16][132];   // +4 pad: conflict-free transposed stores
    __shared__ float Bs[16][128];

    const float* Ap = (MODE == 0) ? A : g_Y;

    const int bm = blockIdx.y * 128;
    const int bn = blockIdx.x * 128;
    const int tid = threadIdx.x;
    const int tx = tid & 15;
    const int ty = tid >> 4;

    float acc[2][2][4][4];
    #pragma unroll
    for (int a = 0; a < 2; a++)
        #pragma unroll
        for (int b2 = 0; b2 < 2; b2++)
            #pragma unroll
            for (int i = 0; i < 4; i++)
                #pragma unroll
                for (int j = 0; j < 4; j++)
                    acc[a][b2][i][j] = 0.f;

    const int ar = tid >> 2;           // 0..63 (row within half-tile)
    const int ac = (tid & 3) * 4;      // k offset 0,4,8,12
    const int br = tid >> 5;           // 0..7
    const int bc = (tid & 31) * 4;     // 0..124

    for (int k0 = 0; k0 < K; k0 += 16) {
        #pragma unroll
        for (int p = 0; p < 2; p++) {
            float4 a4 = *(const float4*)&Ap[(size_t)(bm + p*64 + ar) * K + k0 + ac];
            As[ac+0][p*64+ar] = a4.x;
            As[ac+1][p*64+ar] = a4.y;
            As[ac+2][p*64+ar] = a4.z;
            As[ac+3][p*64+ar] = a4.w;
            *(float4*)&Bs[p*8+br][bc] =
                *(const float4*)&W[(size_t)(k0 + p*8 + br) * N + bn + bc];
        }
        __syncthreads();

        #pragma unroll
        for (int kk = 0; kk < 16; kk++) {
            float af[2][4], bf[2][4];
            *(float4*)af[0] = *(const float4*)&As[kk][ty*4];
            *(float4*)af[1] = *(const float4*)&As[kk][64 + ty*4];
            *(float4*)bf[0] = *(const float4*)&Bs[kk][tx*4];
            *(float4*)bf[1] = *(const float4*)&Bs[kk][64 + tx*4];
            #pragma unroll
            for (int a = 0; a < 2; a++)
                #pragma unroll
                for (int i = 0; i < 4; i++)
                    #pragma unroll
                    for (int b2 = 0; b2 < 2; b2++)
                        #pragma unroll
                        for (int j = 0; j < 4; j++)
                            acc[a][b2][i][j] += af[a][i] * bf[b2][j];
        }
        __syncthreads();
    }

    // Epilogue
    #pragma unroll
    for (int a = 0; a < 2; a++)
        #pragma unroll
        for (int i = 0; i < 4; i++) {
            const int gm = bm + a*64 + ty*4 + i;
            #pragma unroll
            for (int b2 = 0; b2 < 2; b2++)
                #pragma unroll
                for (int j = 0; j < 4; j++) {
                    const int gn = bn + b2*64 + tx*4 + j;
                    float v = acc[a][b2][i][j] + bias[gn];
                    if (MODE == 0) {
                        // gn in [0,3072): which (q/k/v), head, dim
                        const int which = gn >> 10;        // / 1024
                        const int c = gn & 1023;
                        const int h = c >> 6, d = c & 63;
                        const int b = gm >> 11;            // / 2048
                        const int t = gm & 2047;
                        const size_t idx = ((size_t)((b*HH + h)*TT + t))*DH + d;
                        if (which == 0)      g_Q[idx] = v;
                        else if (which == 1) g_K[idx] = v;
                        else                 g_V[idx] = v;
                    } else {
                        out[(size_t)gm * N + gn] = v;
                    }
                }
        }
}

// ---------------------------------------------------------------------------
// Flash attention: 128 queries/block, 1 thread per query row.
// q/acc/s in registers; 64x64 K,V tiles in smem (broadcast reads).
// ---------------------------------------------------------------------------
__global__ __launch_bounds__(128) void attn_kernel()
{
    __shared__ float Ks[64][64];
    __shared__ float Vs[64][64];

    const int bh  = blockIdx.y;           // b*H + h
    const int qt  = blockIdx.x;           // query tile (128 rows each)
    const int tid = threadIdx.x;
    const int t   = qt * 128 + tid;       // global query index

    const float* Qp = g_Q + (size_t)bh * TT * DH;
    const float* Kp = g_K + (size_t)bh * TT * DH;
    const float* Vp = g_V + (size_t)bh * TT * DH;

    float q[64];
    #pragma unroll
    for (int d4 = 0; d4 < 16; d4++) {
        float4 v4 = *(const float4*)&Qp[(size_t)t * DH + d4*4];
        q[d4*4+0] = v4.x; q[d4*4+1] = v4.y; q[d4*4+2] = v4.z; q[d4*4+3] = v4.w;
    }

    float m = -1e30f, l = 0.f;
    float acc[64];
    #pragma unroll
    for (int d = 0; d < 64; d++) acc[d] = 0.f;

    const float scale = 0.125f;           // 1/sqrt(64)
    const int n_tiles = qt*2 + 2;         // causal: keys up to qt*128+127

    for (int kt = 0; kt < n_tiles; kt++) {
        // Cooperative load of K,V tiles: 1024 float4 each, 8 per thread
        #pragma unroll
        for (int i = 0; i < 8; i++) {
            const int f  = i*128 + tid;
            const int r  = f >> 4;
            const int c4 = (f & 15) * 4;
            *(float4*)&Ks[r][c4] = *(const float4*)&Kp[(size_t)(kt*64 + r)*DH + c4];
            *(float4*)&Vs[r][c4] = *(const float4*)&Vp[(size_t)(kt*64 + r)*DH + c4];
        }
        __syncthreads();

        if (kt*64 <= t) {  // warps entirely above the diagonal skip compute
            float s[64];
            #pragma unroll
            for (int j = 0; j < 64; j++) {
                float sum = 0.f;
                #pragma unroll
                for (int d = 0; d < 64; d++) sum += q[d] * Ks[j][d];
                s[j] = (kt*64 + j <= t) ? sum * scale : -1e30f;
            }
            float tmax = -1e30f;
            #pragma unroll
            for (int j = 0; j < 64; j++) tmax = fmaxf(tmax, s[j]);
            const float m_new = fmaxf(m, tmax);
            const float corr = __expf(m - m_new);
            l *= corr;
            #pragma unroll
            for (int d = 0; d < 64; d++) acc[d] *= corr;
            float psum = 0.f;
            #pragma unroll
            for (int j = 0; j < 64; j++) {
                const float p = __expf(s[j] - m_new);
                s[j] = p;
                psum += p;
            }
            l += psum;
            m = m_new;
            #pragma unroll
            for (int j = 0; j < 64; j++)
                #pragma unroll
                for (int d = 0; d < 64; d++)
                    acc[d] += s[j] * Vs[j][d];
        }
        __syncthreads();
    }

    const float inv = 1.0f / l;
    const int b = bh / HH, h = bh % HH;
    float* yp = g_Y + ((size_t)(b*TT + t))*CC + h*DH;
    #pragma unroll
    for (int d4 = 0; d4 < 16; d4++) {
        float4 o;
        o.x = acc[d4*4+0]*inv; o.y = acc[d4*4+1]*inv;
        o.z = acc[d4*4+2]*inv; o.w = acc[d4*4+3]*inv;
        *(float4*)&yp[d4*4] = o;
    }
}

// ---------------------------------------------------------------------------
extern "C" void kernel_launch(void* const* d_in, const int* in_sizes, int n_in,
                              void* d_out, int out_size)
{
    const float* x      = (const float*)d_in[0];
    const float* W_attn = (const float*)d_in[1];
    const float* b_attn = (const float*)d_in[2];
    const float* W_proj = (const float*)d_in[3];
    const float* b_proj = (const float*)d_in[4];
    float* out = (float*)d_out;

    // 1) QKV GEMM + scatter into [B,H,T,D]
    sgemm_kernel<0><<<dim3(3*CC/128, MM/128), 256>>>(x, W_attn, b_attn, nullptr, 3*CC);
    // 2) Causal flash attention
    attn_kernel<<<dim3(TT/128, BB*HH), 128>>>();
    // 3) Output projection
    sgemm_kernel<1><<<dim3(CC/128, MM/128), 256>>>(nullptr, W_proj, b_proj, out, CC);
}

// round 4
// speedup vs baseline: 1.6218x; 1.6218x over previous
#include <cuda_runtime.h>

// Problem constants
#define BB 4
#define TT 2048
#define CC 1024
#define HH 16
#define DH 64
#define MM (BB*TT)          // 8192 rows for both GEMMs

// Scratch (device globals — no allocation allowed)
__device__ float g_Q[BB*HH*TT*DH];   // [B,H,T,D]
__device__ float g_K[BB*HH*TT*DH];
__device__ float g_V[BB*HH*TT*DH];
__device__ float g_Y[BB*TT*CC];      // attention output, [B,T,C]

// ---------------------------------------------------------------------------
// 128x128x16 register-blocked SGEMM. MODE 0: QKV (scatter epilogue into
// g_Q/g_K/g_V with [B,H,T,D] layout). MODE 1: proj (A = g_Y, write out).
// ---------------------------------------------------------------------------
template<int MODE>
__global__ __launch_bounds__(256) void sgemm_kernel(const float* __restrict__ A,
                                                    const float* __restrict__ W,
                                                    const float* __restrict__ bias,
                                                    float* __restrict__ out,
                                                    int N)
{
    const int K = CC;
    __shared__ float As[16][132];   // +4 pad: conflict-free transposed stores
    __shared__ float Bs[16][128];

    const float* Ap = (MODE == 0) ? A : g_Y;

    const int bm = blockIdx.y * 128;
    const int bn = blockIdx.x * 128;
    const int tid = threadIdx.x;
    const int tx = tid & 15;
    const int ty = tid >> 4;

    float acc[2][2][4][4];
    #pragma unroll
    for (int a = 0; a < 2; a++)
        #pragma unroll
        for (int b2 = 0; b2 < 2; b2++)
            #pragma unroll
            for (int i = 0; i < 4; i++)
                #pragma unroll
                for (int j = 0; j < 4; j++)
                    acc[a][b2][i][j] = 0.f;

    const int ar = tid >> 2;           // 0..63 (row within half-tile)
    const int ac = (tid & 3) * 4;      // k offset 0,4,8,12
    const int br = tid >> 5;           // 0..7
    const int bc = (tid & 31) * 4;     // 0..124

    for (int k0 = 0; k0 < K; k0 += 16) {
        #pragma unroll
        for (int p = 0; p < 2; p++) {
            float4 a4 = *(const float4*)&Ap[(size_t)(bm + p*64 + ar) * K + k0 + ac];
            As[ac+0][p*64+ar] = a4.x;
            As[ac+1][p*64+ar] = a4.y;
            As[ac+2][p*64+ar] = a4.z;
            As[ac+3][p*64+ar] = a4.w;
            *(float4*)&Bs[p*8+br][bc] =
                *(const float4*)&W[(size_t)(k0 + p*8 + br) * N + bn + bc];
        }
        __syncthreads();

        #pragma unroll
        for (int kk = 0; kk < 16; kk++) {
            float af[2][4], bf[2][4];
            *(float4*)af[0] = *(const float4*)&As[kk][ty*4];
            *(float4*)af[1] = *(const float4*)&As[kk][64 + ty*4];
            *(float4*)bf[0] = *(const float4*)&Bs[kk][tx*4];
            *(float4*)bf[1] = *(const float4*)&Bs[kk][64 + tx*4];
            #pragma unroll
            for (int a = 0; a < 2; a++)
                #pragma unroll
                for (int i = 0; i < 4; i++)
                    #pragma unroll
                    for (int b2 = 0; b2 < 2; b2++)
                        #pragma unroll
                        for (int j = 0; j < 4; j++)
                            acc[a][b2][i][j] += af[a][i] * bf[b2][j];
        }
        __syncthreads();
    }

    // Epilogue
    #pragma unroll
    for (int a = 0; a < 2; a++)
        #pragma unroll
        for (int i = 0; i < 4; i++) {
            const int gm = bm + a*64 + ty*4 + i;
            #pragma unroll
            for (int b2 = 0; b2 < 2; b2++)
                #pragma unroll
                for (int j = 0; j < 4; j++) {
                    const int gn = bn + b2*64 + tx*4 + j;
                    float v = acc[a][b2][i][j] + bias[gn];
                    if (MODE == 0) {
                        const int which = gn >> 10;        // / 1024
                        const int c = gn & 1023;
                        const int h = c >> 6, d = c & 63;
                        const int b = gm >> 11;            // / 2048
                        const int t = gm & 2047;
                        const size_t idx = ((size_t)((b*HH + h)*TT + t))*DH + d;
                        if (which == 0)      g_Q[idx] = v;
                        else if (which == 1) g_K[idx] = v;
                        else                 g_V[idx] = v;
                    } else {
                        out[(size_t)gm * N + gn] = v;
                    }
                }
        }
}

// ---------------------------------------------------------------------------
// Flash attention v2: register-blocked SIMT.
// Block = 256 threads (16x16), tile = 64 queries x 64 keys, D=64.
// Each thread owns 4x4 of S and 4x4 of O. Both GEMMs are outer-product form
// with float4 smem reads (2 LDS128 per 16 FFMA).
// Smem: Qs^T [d][q], Ks^T [d][k] (aliased with P [q][k] after S phase),
// Vs [k][d]. Row stride 68 floats (16B-aligned, conflict-mitigating pad).
// ---------------------------------------------------------------------------
#define AST 68                       // smem row stride in floats
#define ATTN_SMEM (3*64*AST*4)       // bytes

__global__ __launch_bounds__(256) void attn2_kernel()
{
    extern __shared__ float sm[];
    float* Qs = sm;                  // [64][AST]  Qs[d*AST + q]
    float* Ks = sm + 64*AST;         // [64][AST]  Ks[d*AST + k]   (aliased by Ps)
    float* Vs = sm + 2*64*AST;       // [64][AST]  Vs[k*AST + d]
    float* Ps = Ks;                  // [64][AST]  Ps[q*AST + k]

    const int bh  = blockIdx.y;      // b*H + h
    const int qt  = blockIdx.x;      // 64-query tile index
    const int tid = threadIdx.x;
    const int tx  = tid & 15;
    const int ty  = tid >> 4;
    const int qbase = qt * 64;

    const float* Qp = g_Q + (size_t)bh * TT * DH;
    const float* Kp = g_K + (size_t)bh * TT * DH;
    const float* Vp = g_V + (size_t)bh * TT * DH;

    // Load Q tile transposed into Qs[d][q] (once)
    {
        const int row = tid >> 2;            // query 0..63
        #pragma unroll
        for (int i = 0; i < 4; i++) {
            const int d4 = (tid & 3) + 4*i;  // 0..15
            float4 v = *(const float4*)&Qp[(size_t)(qbase + row) * DH + d4*4];
            Qs[(d4*4+0)*AST + row] = v.x;
            Qs[(d4*4+1)*AST + row] = v.y;
            Qs[(d4*4+2)*AST + row] = v.z;
            Qs[(d4*4+3)*AST + row] = v.w;
        }
    }

    float acc[4][4];
    float m_r[4], l_r[4];
    #pragma unroll
    for (int i = 0; i < 4; i++) {
        m_r[i] = -1e30f; l_r[i] = 0.f;
        #pragma unroll
        for (int j = 0; j < 4; j++) acc[i][j] = 0.f;
    }

    const float scale = 0.125f;              // 1/sqrt(64)

    for (int kt = 0; kt <= qt; kt++) {
        // ---- Load K tile transposed + V tile natural ----
        {
            const int row = tid >> 2;        // key 0..63
            #pragma unroll
            for (int i = 0; i < 4; i++) {
                const int d4 = (tid & 3) + 4*i;
                float4 kv = *(const float4*)&Kp[(size_t)(kt*64 + row) * DH + d4*4];
                Ks[(d4*4+0)*AST + row] = kv.x;
                Ks[(d4*4+1)*AST + row] = kv.y;
                Ks[(d4*4+2)*AST + row] = kv.z;
                Ks[(d4*4+3)*AST + row] = kv.w;
                float4 vv = *(const float4*)&Vp[(size_t)(kt*64 + row) * DH + d4*4];
                *(float4*)&Vs[row*AST + d4*4] = vv;
            }
        }
        __syncthreads();

        // ---- S = Q K^T (outer product over d) ----
        float s[4][4];
        #pragma unroll
        for (int i = 0; i < 4; i++)
            #pragma unroll
            for (int j = 0; j < 4; j++) s[i][j] = 0.f;

        #pragma unroll 8
        for (int d = 0; d < 64; d++) {
            float aq[4], bk[4];
            *(float4*)aq = *(const float4*)&Qs[d*AST + ty*4];
            *(float4*)bk = *(const float4*)&Ks[d*AST + tx*4];
            #pragma unroll
            for (int i = 0; i < 4; i++)
                #pragma unroll
                for (int j = 0; j < 4; j++)
                    s[i][j] += aq[i] * bk[j];
        }
        __syncthreads();   // all Ks reads done (Ps aliases Ks)

        // ---- scale + causal mask (diagonal tile only) ----
        if (kt == qt) {
            #pragma unroll
            for (int i = 0; i < 4; i++)
                #pragma unroll
                for (int j = 0; j < 4; j++)
                    s[i][j] = (tx*4 + j <= ty*4 + i) ? s[i][j] * scale : -1e30f;
        } else {
            #pragma unroll
            for (int i = 0; i < 4; i++)
                #pragma unroll
                for (int j = 0; j < 4; j++)
                    s[i][j] *= scale;
        }

        // ---- online softmax; row stats reduced across the 16 tx lanes ----
        #pragma unroll
        for (int i = 0; i < 4; i++) {
            float tm = fmaxf(fmaxf(s[i][0], s[i][1]), fmaxf(s[i][2], s[i][3]));
            #pragma unroll
            for (int off = 8; off >= 1; off >>= 1)
                tm = fmaxf(tm, __shfl_xor_sync(0xffffffffu, tm, off));
            const float m_new = fmaxf(m_r[i], tm);
            const float corr = __expf(m_r[i] - m_new);
            float psum = 0.f;
            #pragma unroll
            for (int j = 0; j < 4; j++) {
                const float p = __expf(s[i][j] - m_new);
                s[i][j] = p;
                psum += p;
            }
            #pragma unroll
            for (int off = 8; off >= 1; off >>= 1)
                psum += __shfl_xor_sync(0xffffffffu, psum, off);
            l_r[i] = l_r[i] * corr + psum;
            m_r[i] = m_new;
            #pragma unroll
            for (int j = 0; j < 4; j++) acc[i][j] *= corr;
            // stage P row fragment to smem (overwrites Ks region)
            *(float4*)&Ps[(ty*4 + i)*AST + tx*4] = make_float4(s[i][0], s[i][1], s[i][2], s[i][3]);
        }
        __syncthreads();

        // ---- O += P V (outer product over k, 4 k-steps at a time) ----
        #pragma unroll 4
        for (int k0 = 0; k0 < 64; k0 += 4) {
            float ap[4][4], bv[4][4];
            #pragma unroll
            for (int i = 0; i < 4; i++)
                *(float4*)ap[i] = *(const float4*)&Ps[(ty*4 + i)*AST + k0];
            #pragma unroll
            for (int kk = 0; kk < 4; kk++)
                *(float4*)bv[kk] = *(const float4*)&Vs[(k0 + kk)*AST + tx*4];
            #pragma unroll
            for (int i = 0; i < 4; i++)
                #pragma unroll
                for (int kk = 0; kk < 4; kk++)
                    #pragma unroll
                    for (int j = 0; j < 4; j++)
                        acc[i][j] += ap[i][kk] * bv[kk][j];
        }
        __syncthreads();   // before next tile overwrites Ks/Vs
    }

    // ---- epilogue: normalize and write to g_Y [B,T,C] ----
    const int b = bh >> 4, h = bh & 15;
    #pragma unroll
    for (int i = 0; i < 4; i++) {
        const float inv = 1.0f / l_r[i];
        const int q = qbase + ty*4 + i;
        float4 o;
        o.x = acc[i][0]*inv; o.y = acc[i][1]*inv;
        o.z = acc[i][2]*inv; o.w = acc[i][3]*inv;
        *(float4*)&g_Y[((size_t)(b*TT + q))*CC + h*DH + tx*4] = o;
    }
}

// ---------------------------------------------------------------------------
extern "C" void kernel_launch(void* const* d_in, const int* in_sizes, int n_in,
                              void* d_out, int out_size)
{
    const float* x      = (const float*)d_in[0];
    const float* W_attn = (const float*)d_in[1];
    const float* b_attn = (const float*)d_in[2];
    const float* W_proj = (const float*)d_in[3];
    const float* b_proj = (const float*)d_in[4];
    float* out = (float*)d_out;

    static bool attr_set = false;
    if (!attr_set) {
        cudaFuncSetAttribute(attn2_kernel,
                             cudaFuncAttributeMaxDynamicSharedMemorySize, ATTN_SMEM);
        attr_set = true;
    }

    // 1) QKV GEMM + scatter into [B,H,T,D]
    sgemm_kernel<0><<<dim3(3*CC/128, MM/128), 256>>>(x, W_attn, b_attn, nullptr, 3*CC);
    // 2) Causal flash attention (register-blocked)
    attn2_kernel<<<dim3(TT/64, BB*HH), 256, ATTN_SMEM>>>();
    // 3) Output projection
    sgemm_kernel<1><<<dim3(CC/128, MM/128), 256>>>(nullptr, W_proj, b_proj, out, CC);
}

// round 5
// speedup vs baseline: 2.3105x; 1.4246x over previous
#include <cuda_runtime.h>
#include <cuda_bf16.h>
#include <cstdint>

// Problem constants
#define BB 4
#define TT 2048
#define CC 1024
#define HH 16
#define DH 64
#define MM (BB*TT)          // 8192 rows for both GEMMs

// Scratch (device globals — no allocation allowed)
__device__ float g_Q[BB*HH*TT*DH];   // [B,H,T,D]
__device__ float g_K[BB*HH*TT*DH];
__device__ float g_V[BB*HH*TT*DH];
__device__ float g_Y[BB*TT*CC];      // attention output, [B,T,C]

// ---------------------------------------------------------------------------
// mma.sync / ldmatrix primitives
// ---------------------------------------------------------------------------
__device__ __forceinline__ uint32_t smem_u32(const void* p) {
    return (uint32_t)__cvta_generic_to_shared(p);
}
__device__ __forceinline__ void ldsm4(uint32_t& r0, uint32_t& r1, uint32_t& r2, uint32_t& r3, uint32_t a) {
    asm volatile("ldmatrix.sync.aligned.m8n8.x4.shared.b16 {%0,%1,%2,%3},[%4];"
                 : "=r"(r0), "=r"(r1), "=r"(r2), "=r"(r3) : "r"(a));
}
__device__ __forceinline__ void ldsm4t(uint32_t& r0, uint32_t& r1, uint32_t& r2, uint32_t& r3, uint32_t a) {
    asm volatile("ldmatrix.sync.aligned.m8n8.x4.trans.shared.b16 {%0,%1,%2,%3},[%4];"
                 : "=r"(r0), "=r"(r1), "=r"(r2), "=r"(r3) : "r"(a));
}
__device__ __forceinline__ void mma16816(float* c, uint32_t a0, uint32_t a1, uint32_t a2, uint32_t a3,
                                         uint32_t b0, uint32_t b1) {
    asm volatile("mma.sync.aligned.m16n8k16.row.col.f32.bf16.bf16.f32 "
                 "{%0,%1,%2,%3},{%4,%5,%6,%7},{%8,%9},{%0,%1,%2,%3};"
                 : "+f"(c[0]), "+f"(c[1]), "+f"(c[2]), "+f"(c[3])
                 : "r"(a0), "r"(a1), "r"(a2), "r"(a3), "r"(b0), "r"(b1));
}
__device__ __forceinline__ uint32_t pack_bf16(float x, float y) {
    __nv_bfloat162 t = __floats2bfloat162_rn(x, y);
    return *(uint32_t*)&t;
}
// split (x,y) into bf16 hi pair + bf16 lo (residual) pair
__device__ __forceinline__ void split2(float x, float y, uint32_t& h, uint32_t& l) {
    float hx = __bfloat162float(__float2bfloat16(x));
    float hy = __bfloat162float(__float2bfloat16(y));
    h = pack_bf16(hx, hy);
    l = pack_bf16(x - hx, y - hy);
}

// ---------------------------------------------------------------------------
// Tensor-core GEMM (3x bf16 split precision = fp32-class accuracy).
// Block 128x128x64, 256 threads, 8 warps (4m x 2n), warp tile 32x64.
// MODE 0: QKV (scatter into g_Q/g_K/g_V). MODE 1: proj (A = g_Y, write out).
// Smem: bf16 hi/lo tiles, XOR-swizzled for conflict-free ldmatrix.
//   A[m][k]: byte = m*128 + ((k>>3)^(m&7))*16 + (k&7)*2      (128B rows)
//   B[k][n]: byte = k*256 + ((n>>3)^(k&7))*16 + (n&7)*2      (256B rows)
// ---------------------------------------------------------------------------
#define GEMM_SMEM 65536

template<int MODE>
__global__ __launch_bounds__(256) void hgemm_kernel(const float* __restrict__ A,
                                                    const float* __restrict__ W,
                                                    const float* __restrict__ bias,
                                                    float* __restrict__ out,
                                                    int N)
{
    extern __shared__ char smg[];
    char* sAh = smg;                 // 128*64*2 = 16KB
    char* sAl = smg + 16384;
    char* sBh = smg + 32768;         // 64*128*2 = 16KB
    char* sBl = smg + 49152;
    const uint32_t uAh = smem_u32(sAh), uAl = smem_u32(sAl);
    const uint32_t uBh = smem_u32(sBh), uBl = smem_u32(sBl);

    const float* Ap = (MODE == 0) ? A : g_Y;

    const int bm = blockIdx.y * 128;
    const int bn = blockIdx.x * 128;
    const int tid  = threadIdx.x;
    const int wid  = tid >> 5;
    const int lane = tid & 31;
    const int warp_m = wid & 3;       // 0..3 -> m offset *32
    const int warp_n = wid >> 2;      // 0..1 -> n offset *64

    float acc[2][8][4];
    #pragma unroll
    for (int mt = 0; mt < 2; mt++)
        #pragma unroll
        for (int nt = 0; nt < 8; nt++)
            #pragma unroll
            for (int r = 0; r < 4; r++) acc[mt][nt][r] = 0.f;

    for (int k0 = 0; k0 < CC; k0 += 64) {
        // ---- load A tile 128x64 fp32 -> bf16 hi/lo smem ----
        {
            const float* Asrc = Ap + (size_t)bm * CC + k0;
            #pragma unroll
            for (int i = 0; i < 8; i++) {
                const int idx = i * 256 + tid;
                const int m  = idx >> 4;
                const int kk = (idx & 15) * 4;
                float4 v = *(const float4*)&Asrc[(size_t)m * CC + kk];
                uint32_t h01, l01, h23, l23;
                split2(v.x, v.y, h01, l01);
                split2(v.z, v.w, h23, l23);
                const int off = m * 128 + (((kk >> 3) ^ (m & 7)) << 4) + (kk & 7) * 2;
                *(uint2*)(sAh + off) = make_uint2(h01, h23);
                *(uint2*)(sAl + off) = make_uint2(l01, l23);
            }
        }
        // ---- load B tile 64x128 fp32 -> bf16 hi/lo smem ----
        {
            #pragma unroll
            for (int i = 0; i < 8; i++) {
                const int idx = i * 256 + tid;
                const int k  = idx >> 5;
                const int nn = (idx & 31) * 4;
                float4 v = *(const float4*)&W[(size_t)(k0 + k) * N + bn + nn];
                uint32_t h01, l01, h23, l23;
                split2(v.x, v.y, h01, l01);
                split2(v.z, v.w, h23, l23);
                const int off = k * 256 + (((nn >> 3) ^ (k & 7)) << 4) + (nn & 7) * 2;
                *(uint2*)(sBh + off) = make_uint2(h01, h23);
                *(uint2*)(sBl + off) = make_uint2(l01, l23);
            }
        }
        __syncthreads();

        // ---- compute: 4 k-steps of 16 ----
        #pragma unroll
        for (int ks = 0; ks < 64; ks += 16) {
            uint32_t ah[2][4], al[2][4];
            #pragma unroll
            for (int mt = 0; mt < 2; mt++) {
                const int m = warp_m * 32 + mt * 16 + (lane & 15);
                const int k = ks + (lane >> 4) * 8;
                const uint32_t off = m * 128 + (((k >> 3) ^ (m & 7)) << 4);
                ldsm4(ah[mt][0], ah[mt][1], ah[mt][2], ah[mt][3], uAh + off);
                ldsm4(al[mt][0], al[mt][1], al[mt][2], al[mt][3], uAl + off);
            }
            uint32_t bh[8][2], bl[8][2];
            #pragma unroll
            for (int p = 0; p < 4; p++) {
                const int k = ks + ((lane >> 3) & 1) * 8 + (lane & 7);
                const int n = warp_n * 64 + p * 16 + (lane >> 4) * 8;
                const uint32_t off = k * 256 + (((n >> 3) ^ (k & 7)) << 4);
                ldsm4t(bh[2*p][0], bh[2*p][1], bh[2*p+1][0], bh[2*p+1][1], uBh + off);
                ldsm4t(bl[2*p][0], bl[2*p][1], bl[2*p+1][0], bl[2*p+1][1], uBl + off);
            }
            #pragma unroll
            for (int mt = 0; mt < 2; mt++)
                #pragma unroll
                for (int nt = 0; nt < 8; nt++) {
                    mma16816(acc[mt][nt], ah[mt][0], ah[mt][1], ah[mt][2], ah[mt][3],
                             bh[nt][0], bh[nt][1]);                       // hi*hi
                    mma16816(acc[mt][nt], ah[mt][0], ah[mt][1], ah[mt][2], ah[mt][3],
                             bl[nt][0], bl[nt][1]);                       // hi*lo
                    mma16816(acc[mt][nt], al[mt][0], al[mt][1], al[mt][2], al[mt][3],
                             bh[nt][0], bh[nt][1]);                       // lo*hi
                }
        }
        __syncthreads();
    }

    // ---- epilogue ----
    const int g  = lane >> 2;
    const int tg = lane & 3;
    #pragma unroll
    for (int mt = 0; mt < 2; mt++)
        #pragma unroll
        for (int nt = 0; nt < 8; nt++) {
            const int gn = bn + warp_n * 64 + nt * 8 + tg * 2;
            #pragma unroll
            for (int half = 0; half < 2; half++) {
                const int gm = bm + warp_m * 32 + mt * 16 + g + half * 8;
                #pragma unroll
                for (int jj = 0; jj < 2; jj++) {
                    const float v = acc[mt][nt][half * 2 + jj] + bias[gn + jj];
                    if (MODE == 0) {
                        const int gnn = gn + jj;
                        const int which = gnn >> 10;
                        const int c = gnn & 1023;
                        const int h = c >> 6, d = c & 63;
                        const int b = gm >> 11;
                        const int t = gm & 2047;
                        const size_t idx = ((size_t)((b*HH + h)*TT + t))*DH + d;
                        if (which == 0)      g_Q[idx] = v;
                        else if (which == 1) g_K[idx] = v;
                        else                 g_V[idx] = v;
                    } else {
                        out[(size_t)gm * N + gn + jj] = v;
                    }
                }
            }
        }
}

// ---------------------------------------------------------------------------
// Flash attention (register-blocked SIMT) — unchanged from R3.
// ---------------------------------------------------------------------------
#define AST 68
#define ATTN_SMEM (3*64*AST*4)

__global__ __launch_bounds__(256) void attn2_kernel()
{
    extern __shared__ float sm[];
    float* Qs = sm;
    float* Ks = sm + 64*AST;
    float* Vs = sm + 2*64*AST;
    float* Ps = Ks;

    const int bh  = blockIdx.y;
    const int qt  = blockIdx.x;
    const int tid = threadIdx.x;
    const int tx  = tid & 15;
    const int ty  = tid >> 4;
    const int qbase = qt * 64;

    const float* Qp = g_Q + (size_t)bh * TT * DH;
    const float* Kp = g_K + (size_t)bh * TT * DH;
    const float* Vp = g_V + (size_t)bh * TT * DH;

    {
        const int row = tid >> 2;
        #pragma unroll
        for (int i = 0; i < 4; i++) {
            const int d4 = (tid & 3) + 4*i;
            float4 v = *(const float4*)&Qp[(size_t)(qbase + row) * DH + d4*4];
            Qs[(d4*4+0)*AST + row] = v.x;
            Qs[(d4*4+1)*AST + row] = v.y;
            Qs[(d4*4+2)*AST + row] = v.z;
            Qs[(d4*4+3)*AST + row] = v.w;
        }
    }

    float acc[4][4];
    float m_r[4], l_r[4];
    #pragma unroll
    for (int i = 0; i < 4; i++) {
        m_r[i] = -1e30f; l_r[i] = 0.f;
        #pragma unroll
        for (int j = 0; j < 4; j++) acc[i][j] = 0.f;
    }

    const float scale = 0.125f;

    for (int kt = 0; kt <= qt; kt++) {
        {
            const int row = tid >> 2;
            #pragma unroll
            for (int i = 0; i < 4; i++) {
                const int d4 = (tid & 3) + 4*i;
                float4 kv = *(const float4*)&Kp[(size_t)(kt*64 + row) * DH + d4*4];
                Ks[(d4*4+0)*AST + row] = kv.x;
                Ks[(d4*4+1)*AST + row] = kv.y;
                Ks[(d4*4+2)*AST + row] = kv.z;
                Ks[(d4*4+3)*AST + row] = kv.w;
                float4 vv = *(const float4*)&Vp[(size_t)(kt*64 + row) * DH + d4*4];
                *(float4*)&Vs[row*AST + d4*4] = vv;
            }
        }
        __syncthreads();

        float s[4][4];
        #pragma unroll
        for (int i = 0; i < 4; i++)
            #pragma unroll
            for (int j = 0; j < 4; j++) s[i][j] = 0.f;

        #pragma unroll 8
        for (int d = 0; d < 64; d++) {
            float aq[4], bk[4];
            *(float4*)aq = *(const float4*)&Qs[d*AST + ty*4];
            *(float4*)bk = *(const float4*)&Ks[d*AST + tx*4];
            #pragma unroll
            for (int i = 0; i < 4; i++)
                #pragma unroll
                for (int j = 0; j < 4; j++)
                    s[i][j] += aq[i] * bk[j];
        }
        __syncthreads();

        if (kt == qt) {
            #pragma unroll
            for (int i = 0; i < 4; i++)
                #pragma unroll
                for (int j = 0; j < 4; j++)
                    s[i][j] = (tx*4 + j <= ty*4 + i) ? s[i][j] * scale : -1e30f;
        } else {
            #pragma unroll
            for (int i = 0; i < 4; i++)
                #pragma unroll
                for (int j = 0; j < 4; j++)
                    s[i][j] *= scale;
        }

        #pragma unroll
        for (int i = 0; i < 4; i++) {
            float tm = fmaxf(fmaxf(s[i][0], s[i][1]), fmaxf(s[i][2], s[i][3]));
            #pragma unroll
            for (int off = 8; off >= 1; off >>= 1)
                tm = fmaxf(tm, __shfl_xor_sync(0xffffffffu, tm, off));
            const float m_new = fmaxf(m_r[i], tm);
            const float corr = __expf(m_r[i] - m_new);
            float psum = 0.f;
            #pragma unroll
            for (int j = 0; j < 4; j++) {
                const float p = __expf(s[i][j] - m_new);
                s[i][j] = p;
                psum += p;
            }
            #pragma unroll
            for (int off = 8; off >= 1; off >>= 1)
                psum += __shfl_xor_sync(0xffffffffu, psum, off);
            l_r[i] = l_r[i] * corr + psum;
            m_r[i] = m_new;
            #pragma unroll
            for (int j = 0; j < 4; j++) acc[i][j] *= corr;
            *(float4*)&Ps[(ty*4 + i)*AST + tx*4] = make_float4(s[i][0], s[i][1], s[i][2], s[i][3]);
        }
        __syncthreads();

        #pragma unroll 4
        for (int k0 = 0; k0 < 64; k0 += 4) {
            float ap[4][4], bv[4][4];
            #pragma unroll
            for (int i = 0; i < 4; i++)
                *(float4*)ap[i] = *(const float4*)&Ps[(ty*4 + i)*AST + k0];
            #pragma unroll
            for (int kk = 0; kk < 4; kk++)
                *(float4*)bv[kk] = *(const float4*)&Vs[(k0 + kk)*AST + tx*4];
            #pragma unroll
            for (int i = 0; i < 4; i++)
                #pragma unroll
                for (int kk = 0; kk < 4; kk++)
                    #pragma unroll
                    for (int j = 0; j < 4; j++)
                        acc[i][j] += ap[i][kk] * bv[kk][j];
        }
        __syncthreads();
    }

    const int b = bh >> 4, h = bh & 15;
    #pragma unroll
    for (int i = 0; i < 4; i++) {
        const float inv = 1.0f / l_r[i];
        const int q = qbase + ty*4 + i;
        float4 o;
        o.x = acc[i][0]*inv; o.y = acc[i][1]*inv;
        o.z = acc[i][2]*inv; o.w = acc[i][3]*inv;
        *(float4*)&g_Y[((size_t)(b*TT + q))*CC + h*DH + tx*4] = o;
    }
}

// ---------------------------------------------------------------------------
extern "C" void kernel_launch(void* const* d_in, const int* in_sizes, int n_in,
                              void* d_out, int out_size)
{
    const float* x      = (const float*)d_in[0];
    const float* W_attn = (const float*)d_in[1];
    const float* b_attn = (const float*)d_in[2];
    const float* W_proj = (const float*)d_in[3];
    const float* b_proj = (const float*)d_in[4];
    float* out = (float*)d_out;

    static bool attr_set = false;
    if (!attr_set) {
        cudaFuncSetAttribute(attn2_kernel,
                             cudaFuncAttributeMaxDynamicSharedMemorySize, ATTN_SMEM);
        cudaFuncSetAttribute(hgemm_kernel<0>,
                             cudaFuncAttributeMaxDynamicSharedMemorySize, GEMM_SMEM);
        cudaFuncSetAttribute(hgemm_kernel<1>,
                             cudaFuncAttributeMaxDynamicSharedMemorySize, GEMM_SMEM);
        attr_set = true;
    }

    // 1) QKV GEMM (tensor cores, 3x bf16) + scatter into [B,H,T,D]
    hgemm_kernel<0><<<dim3(3*CC/128, MM/128), 256, GEMM_SMEM>>>(x, W_attn, b_attn, nullptr, 3*CC);
    // 2) Causal flash attention
    attn2_kernel<<<dim3(TT/64, BB*HH), 256, ATTN_SMEM>>>();
    // 3) Output projection (tensor cores, 3x bf16)
    hgemm_kernel<1><<<dim3(CC/128, MM/128), 256, GEMM_SMEM>>>(nullptr, W_proj, b_proj, out, CC);
}

// round 7
// speedup vs baseline: 2.3661x; 1.0241x over previous
#include <cuda_runtime.h>
#include <cuda_bf16.h>
#include <cstdint>

// Problem constants
#define BB 4
#define TT 2048
#define CC 1024
#define HH 16
#define DH 64
#define MM (BB*TT)          // 8192 rows for both GEMMs

// Scratch (device globals — no allocation allowed)
__device__ float g_Q[BB*HH*TT*DH];   // [B,H,T,D]
__device__ float g_K[BB*HH*TT*DH];
__device__ float g_V[BB*HH*TT*DH];
__device__ float g_Y[BB*TT*CC];      // attention output, [B,T,C]

// ---------------------------------------------------------------------------
// mma.sync / ldmatrix primitives
// ---------------------------------------------------------------------------
__device__ __forceinline__ uint32_t smem_u32(const void* p) {
    return (uint32_t)__cvta_generic_to_shared(p);
}
__device__ __forceinline__ void ldsm4(uint32_t& r0, uint32_t& r1, uint32_t& r2, uint32_t& r3, uint32_t a) {
    asm volatile("ldmatrix.sync.aligned.m8n8.x4.shared.b16 {%0,%1,%2,%3},[%4];"
                 : "=r"(r0), "=r"(r1), "=r"(r2), "=r"(r3) : "r"(a));
}
__device__ __forceinline__ void ldsm4t(uint32_t& r0, uint32_t& r1, uint32_t& r2, uint32_t& r3, uint32_t a) {
    asm volatile("ldmatrix.sync.aligned.m8n8.x4.trans.shared.b16 {%0,%1,%2,%3},[%4];"
                 : "=r"(r0), "=r"(r1), "=r"(r2), "=r"(r3) : "r"(a));
}
__device__ __forceinline__ void mma16816(float* c, uint32_t a0, uint32_t a1, uint32_t a2, uint32_t a3,
                                         uint32_t b0, uint32_t b1) {
    asm volatile("mma.sync.aligned.m16n8k16.row.col.f32.bf16.bf16.f32 "
                 "{%0,%1,%2,%3},{%4,%5,%6,%7},{%8,%9},{%0,%1,%2,%3};"
                 : "+f"(c[0]), "+f"(c[1]), "+f"(c[2]), "+f"(c[3])
                 : "r"(a0), "r"(a1), "r"(a2), "r"(a3), "r"(b0), "r"(b1));
}
__device__ __forceinline__ uint32_t pack_bf16(float x, float y) {
    __nv_bfloat162 t = __floats2bfloat162_rn(x, y);
    return *(uint32_t*)&t;
}
// split (x,y) into bf16 hi pair + bf16 lo (residual) pair
__device__ __forceinline__ void split2(float x, float y, uint32_t& h, uint32_t& l) {
    float hx = __bfloat162float(__float2bfloat16(x));
    float hy = __bfloat162float(__float2bfloat16(y));
    h = pack_bf16(hx, hy);
    l = pack_bf16(x - hx, y - hy);
}

// ---------------------------------------------------------------------------
// Tensor-core GEMM (3x bf16 split precision). Unchanged from R4.
// ---------------------------------------------------------------------------
#define GEMM_SMEM 65536

template<int MODE>
__global__ __launch_bounds__(256) void hgemm_kernel(const float* __restrict__ A,
                                                    const float* __restrict__ W,
                                                    const float* __restrict__ bias,
                                                    float* __restrict__ out,
                                                    int N)
{
    extern __shared__ char smg[];
    char* sAh = smg;
    char* sAl = smg + 16384;
    char* sBh = smg + 32768;
    char* sBl = smg + 49152;
    const uint32_t uAh = smem_u32(sAh), uAl = smem_u32(sAl);
    const uint32_t uBh = smem_u32(sBh), uBl = smem_u32(sBl);

    const float* Ap = (MODE == 0) ? A : g_Y;

    const int bm = blockIdx.y * 128;
    const int bn = blockIdx.x * 128;
    const int tid  = threadIdx.x;
    const int wid  = tid >> 5;
    const int lane = tid & 31;
    const int warp_m = wid & 3;
    const int warp_n = wid >> 2;

    float acc[2][8][4];
    #pragma unroll
    for (int mt = 0; mt < 2; mt++)
        #pragma unroll
        for (int nt = 0; nt < 8; nt++)
            #pragma unroll
            for (int r = 0; r < 4; r++) acc[mt][nt][r] = 0.f;

    for (int k0 = 0; k0 < CC; k0 += 64) {
        {
            const float* Asrc = Ap + (size_t)bm * CC + k0;
            #pragma unroll
            for (int i = 0; i < 8; i++) {
                const int idx = i * 256 + tid;
                const int m  = idx >> 4;
                const int kk = (idx & 15) * 4;
                float4 v = *(const float4*)&Asrc[(size_t)m * CC + kk];
                uint32_t h01, l01, h23, l23;
                split2(v.x, v.y, h01, l01);
                split2(v.z, v.w, h23, l23);
                const int off = m * 128 + (((kk >> 3) ^ (m & 7)) << 4) + (kk & 7) * 2;
                *(uint2*)(sAh + off) = make_uint2(h01, h23);
                *(uint2*)(sAl + off) = make_uint2(l01, l23);
            }
        }
        {
            #pragma unroll
            for (int i = 0; i < 8; i++) {
                const int idx = i * 256 + tid;
                const int k  = idx >> 5;
                const int nn = (idx & 31) * 4;
                float4 v = *(const float4*)&W[(size_t)(k0 + k) * N + bn + nn];
                uint32_t h01, l01, h23, l23;
                split2(v.x, v.y, h01, l01);
                split2(v.z, v.w, h23, l23);
                const int off = k * 256 + (((nn >> 3) ^ (k & 7)) << 4) + (nn & 7) * 2;
                *(uint2*)(sBh + off) = make_uint2(h01, h23);
                *(uint2*)(sBl + off) = make_uint2(l01, l23);
            }
        }
        __syncthreads();

        #pragma unroll
        for (int ks = 0; ks < 64; ks += 16) {
            uint32_t ah[2][4], al[2][4];
            #pragma unroll
            for (int mt = 0; mt < 2; mt++) {
                const int m = warp_m * 32 + mt * 16 + (lane & 15);
                const int k = ks + (lane >> 4) * 8;
                const uint32_t off = m * 128 + (((k >> 3) ^ (m & 7)) << 4);
                ldsm4(ah[mt][0], ah[mt][1], ah[mt][2], ah[mt][3], uAh + off);
                ldsm4(al[mt][0], al[mt][1], al[mt][2], al[mt][3], uAl + off);
            }
            uint32_t bh[8][2], bl[8][2];
            #pragma unroll
            for (int p = 0; p < 4; p++) {
                const int k = ks + ((lane >> 3) & 1) * 8 + (lane & 7);
                const int n = warp_n * 64 + p * 16 + (lane >> 4) * 8;
                const uint32_t off = k * 256 + (((n >> 3) ^ (k & 7)) << 4);
                ldsm4t(bh[2*p][0], bh[2*p][1], bh[2*p+1][0], bh[2*p+1][1], uBh + off);
                ldsm4t(bl[2*p][0], bl[2*p][1], bl[2*p+1][0], bl[2*p+1][1], uBl + off);
            }
            #pragma unroll
            for (int mt = 0; mt < 2; mt++)
                #pragma unroll
                for (int nt = 0; nt < 8; nt++) {
                    mma16816(acc[mt][nt], ah[mt][0], ah[mt][1], ah[mt][2], ah[mt][3],
                             bh[nt][0], bh[nt][1]);
                    mma16816(acc[mt][nt], ah[mt][0], ah[mt][1], ah[mt][2], ah[mt][3],
                             bl[nt][0], bl[nt][1]);
                    mma16816(acc[mt][nt], al[mt][0], al[mt][1], al[mt][2], al[mt][3],
                             bh[nt][0], bh[nt][1]);
                }
        }
        __syncthreads();
    }

    const int g  = lane >> 2;
    const int tg = lane & 3;
    #pragma unroll
    for (int mt = 0; mt < 2; mt++)
        #pragma unroll
        for (int nt = 0; nt < 8; nt++) {
            const int gn = bn + warp_n * 64 + nt * 8 + tg * 2;
            #pragma unroll
            for (int half = 0; half < 2; half++) {
                const int gm = bm + warp_m * 32 + mt * 16 + g + half * 8;
                #pragma unroll
                for (int jj = 0; jj < 2; jj++) {
                    const float v = acc[mt][nt][half * 2 + jj] + bias[gn + jj];
                    if (MODE == 0) {
                        const int gnn = gn + jj;
                        const int which = gnn >> 10;
                        const int c = gnn & 1023;
                        const int h = c >> 6, d = c & 63;
                        const int b = gm >> 11;
                        const int t = gm & 2047;
                        const size_t idx = ((size_t)((b*HH + h)*TT + t))*DH + d;
                        if (which == 0)      g_Q[idx] = v;
                        else if (which == 1) g_K[idx] = v;
                        else                 g_V[idx] = v;
                    } else {
                        out[(size_t)gm * N + gn + jj] = v;
                    }
                }
            }
        }
}

// ---------------------------------------------------------------------------
// Flash attention v3: tensor-core (mma bf16, 3x split), FA2 layout.
// Block = 8 warps, 128 queries of one (b,h). Key tiles of 64.
// Each warp: 16 queries. Q fragments persistent in registers.
// Smem (32KB): phase 1 = Qh/Ql stage [128][64]bf16; then Kh/Kl/Vh/Vl
// [64][64]bf16 each, all XOR-swizzled 128B rows.
// ---------------------------------------------------------------------------
#define ATT_SMEM 32768

__global__ __launch_bounds__(256) void attn3_kernel()
{
    extern __shared__ char smx[];
    const uint32_t uB = smem_u32(smx);

    const int bh  = blockIdx.y;
    const int qtb = blockIdx.x;          // 128-query tile
    const int qb  = qtb * 128;
    const int tid = threadIdx.x;
    const int wid = tid >> 5;
    const int lane = tid & 31;

    const float* Qp = g_Q + (size_t)bh * TT * DH;
    const float* Kp = g_K + (size_t)bh * TT * DH;
    const float* Vp = g_V + (size_t)bh * TT * DH;

    // ---- stage Q tile (128x64 fp32 -> bf16 hi/lo, swizzled) ----
    #pragma unroll
    for (int i = 0; i < 8; i++) {
        const int c  = i * 256 + tid;        // 2048 float4 chunks
        const int m  = c >> 4;
        const int d4 = (c & 15) * 4;
        float4 v = *(const float4*)&Qp[(size_t)(qb + m) * DH + d4];
        uint32_t h01, l01, h23, l23;
        split2(v.x, v.y, h01, l01);
        split2(v.z, v.w, h23, l23);
        const int off = m * 128 + (((d4 >> 3) ^ (m & 7)) << 4) + (d4 & 7) * 2;
        *(uint2*)(smx + off)         = make_uint2(h01, h23);
        *(uint2*)(smx + 16384 + off) = make_uint2(l01, l23);
    }
    __syncthreads();

    // ---- persistent Q fragments (4 k-steps of 16) ----
    uint32_t qh[4][4], ql[4][4];
    {
        const int m = wid * 16 + (lane & 15);
        #pragma unroll
        for (int ks = 0; ks < 4; ks++) {
            const int k = ks * 16 + (lane >> 4) * 8;
            const uint32_t off = m * 128 + (((k >> 3) ^ (m & 7)) << 4);
            ldsm4(qh[ks][0], qh[ks][1], qh[ks][2], qh[ks][3], uB + off);
            ldsm4(ql[ks][0], ql[ks][1], ql[ks][2], ql[ks][3], uB + 16384 + off);
        }
    }
    __syncthreads();   // Q stage smem now free for K/V

    float oacc[8][4];
    #pragma unroll
    for (int nt = 0; nt < 8; nt++)
        #pragma unroll
        for (int r = 0; r < 4; r++) oacc[nt][r] = 0.f;
    float m0 = -1e30f, m1 = -1e30f, l0 = 0.f, l1 = 0.f;

    const int qw = qb + wid * 16;         // warp's first query row
    const int g  = lane >> 2;
    const int tg = lane & 3;
    const int row0 = qw + g;              // rows this thread owns
    const float scale = 0.125f;
    const int ktmax = 2 * qtb + 1;

    for (int kt = 0; kt <= ktmax; kt++) {
        // ---- cooperative load K,V tile (64x64 fp32 -> bf16 hi/lo) ----
        #pragma unroll
        for (int i = 0; i < 4; i++) {
            const int c  = i * 256 + tid;     // 1024 chunks
            const int r  = c >> 4;            // key row
            const int d4 = (c & 15) * 4;
            const int off = r * 128 + (((d4 >> 3) ^ (r & 7)) << 4) + (d4 & 7) * 2;
            float4 kv = *(const float4*)&Kp[(size_t)(kt*64 + r) * DH + d4];
            uint32_t h01, l01, h23, l23;
            split2(kv.x, kv.y, h01, l01);
            split2(kv.z, kv.w, h23, l23);
            *(uint2*)(smx + off)        = make_uint2(h01, h23);
            *(uint2*)(smx + 8192 + off) = make_uint2(l01, l23);
            float4 vv = *(const float4*)&Vp[(size_t)(kt*64 + r) * DH + d4];
            split2(vv.x, vv.y, h01, l01);
            split2(vv.z, vv.w, h23, l23);
            *(uint2*)(smx + 16384 + off) = make_uint2(h01, h23);
            *(uint2*)(smx + 24576 + off) = make_uint2(l01, l23);
        }
        __syncthreads();

        if (kt * 64 <= qw + 15) {     // warp has at least one unmasked row
            // ---- S = Q K^T ----
            float sacc[8][4];
            #pragma unroll
            for (int nt = 0; nt < 8; nt++)
                #pragma unroll
                for (int r = 0; r < 4; r++) sacc[nt][r] = 0.f;

            #pragma unroll
            for (int ks = 0; ks < 4; ks++) {
                #pragma unroll
                for (int p = 0; p < 4; p++) {       // pairs of 8-key n-tiles
                    const int n = p * 16 + (lane & 15);
                    const int k = ks * 16 + (lane >> 4) * 8;
                    const uint32_t off = n * 128 + (((k >> 3) ^ (n & 7)) << 4);
                    uint32_t b0a, b0b, b1a, b1b;
                    ldsm4(b0a, b0b, b1a, b1b, uB + off);          // Kh
                    mma16816(sacc[2*p  ], qh[ks][0], qh[ks][1], qh[ks][2], qh[ks][3], b0a, b1a);
                    mma16816(sacc[2*p+1], qh[ks][0], qh[ks][1], qh[ks][2], qh[ks][3], b0b, b1b);
                    mma16816(sacc[2*p  ], ql[ks][0], ql[ks][1], ql[ks][2], ql[ks][3], b0a, b1a);
                    mma16816(sacc[2*p+1], ql[ks][0], ql[ks][1], ql[ks][2], ql[ks][3], b0b, b1b);
                    ldsm4(b0a, b0b, b1a, b1b, uB + 8192 + off);   // Kl
                    mma16816(sacc[2*p  ], qh[ks][0], qh[ks][1], qh[ks][2], qh[ks][3], b0a, b1a);
                    mma16816(sacc[2*p+1], qh[ks][0], qh[ks][1], qh[ks][2], qh[ks][3], b0b, b1b);
                }
            }

            // ---- scale + causal mask ----
            if (kt * 64 + 63 > qw) {
                #pragma unroll
                for (int nt = 0; nt < 8; nt++) {
                    const int col = kt * 64 + nt * 8 + tg * 2;
                    sacc[nt][0] = (col     <= row0    ) ? sacc[nt][0] * scale : -1e30f;
                    sacc[nt][1] = (col + 1 <= row0    ) ? sacc[nt][1] * scale : -1e30f;
                    sacc[nt][2] = (col     <= row0 + 8) ? sacc[nt][2] * scale : -1e30f;
                    sacc[nt][3] = (col + 1 <= row0 + 8) ? sacc[nt][3] * scale : -1e30f;
                }
            } else {
                #pragma unroll
                for (int nt = 0; nt < 8; nt++)
                    #pragma unroll
                    for (int r = 0; r < 4; r++) sacc[nt][r] *= scale;
            }

            // ---- online softmax (rows row0 and row0+8) ----
            float mx0 = -1e30f, mx1 = -1e30f;
            #pragma unroll
            for (int nt = 0; nt < 8; nt++) {
                mx0 = fmaxf(mx0, fmaxf(sacc[nt][0], sacc[nt][1]));
                mx1 = fmaxf(mx1, fmaxf(sacc[nt][2], sacc[nt][3]));
            }
            mx0 = fmaxf(mx0, __shfl_xor_sync(0xffffffffu, mx0, 1));
            mx0 = fmaxf(mx0, __shfl_xor_sync(0xffffffffu, mx0, 2));
            mx1 = fmaxf(mx1, __shfl_xor_sync(0xffffffffu, mx1, 1));
            mx1 = fmaxf(mx1, __shfl_xor_sync(0xffffffffu, mx1, 2));
            const float mn0 = fmaxf(m0, mx0);
            const float mn1 = fmaxf(m1, mx1);
            const float corr0 = __expf(m0 - mn0);
            const float corr1 = __expf(m1 - mn1);

            uint32_t ph01[8], ph23[8], pl01[8], pl23[8];
            float ps0 = 0.f, ps1 = 0.f;
            #pragma unroll
            for (int nt = 0; nt < 8; nt++) {
                const float p0 = __expf(sacc[nt][0] - mn0);
                const float p1 = __expf(sacc[nt][1] - mn0);
                const float p2 = __expf(sacc[nt][2] - mn1);
                const float p3 = __expf(sacc[nt][3] - mn1);
                ps0 += p0 + p1;
                ps1 += p2 + p3;
                split2(p0, p1, ph01[nt], pl01[nt]);
                split2(p2, p3, ph23[nt], pl23[nt]);
            }
            ps0 += __shfl_xor_sync(0xffffffffu, ps0, 1);
            ps0 += __shfl_xor_sync(0xffffffffu, ps0, 2);
            ps1 += __shfl_xor_sync(0xffffffffu, ps1, 1);
            ps1 += __shfl_xor_sync(0xffffffffu, ps1, 2);
            l0 = l0 * corr0 + ps0;  m0 = mn0;
            l1 = l1 * corr1 + ps1;  m1 = mn1;
            #pragma unroll
            for (int nt = 0; nt < 8; nt++) {
                oacc[nt][0] *= corr0; oacc[nt][1] *= corr0;
                oacc[nt][2] *= corr1; oacc[nt][3] *= corr1;
            }

            // ---- O += P V ----
            #pragma unroll
            for (int kk = 0; kk < 4; kk++) {        // 16-key k-tiles
                const uint32_t a0 = ph01[2*kk],   a1 = ph23[2*kk];
                const uint32_t a2 = ph01[2*kk+1], a3 = ph23[2*kk+1];
                const uint32_t c0 = pl01[2*kk],   c1 = pl23[2*kk];
                const uint32_t c2 = pl01[2*kk+1], c3 = pl23[2*kk+1];
                #pragma unroll
                for (int dp = 0; dp < 4; dp++) {    // 16-wide d chunks
                    const int r = kk * 16 + (lane & 15);
                    const int d = dp * 16 + (lane >> 4) * 8;
                    const uint32_t off = r * 128 + (((d >> 3) ^ (r & 7)) << 4);
                    uint32_t b0a, b1a, b0b, b1b;
                    ldsm4t(b0a, b1a, b0b, b1b, uB + 16384 + off);   // Vh
                    mma16816(oacc[2*dp  ], a0, a1, a2, a3, b0a, b1a);
                    mma16816(oacc[2*dp+1], a0, a1, a2, a3, b0b, b1b);
                    mma16816(oacc[2*dp  ], c0, c1, c2, c3, b0a, b1a);
                    mma16816(oacc[2*dp+1], c0, c1, c2, c3, b0b, b1b);
                    ldsm4t(b0a, b1a, b0b, b1b, uB + 24576 + off);   // Vl
                    mma16816(oacc[2*dp  ], a0, a1, a2, a3, b0a, b1a);
                    mma16816(oacc[2*dp+1], a0, a1, a2, a3, b0b, b1b);
                }
            }
        }
        __syncthreads();   // before next tile overwrites K/V
    }

    // ---- epilogue: normalize, write g_Y [B,T,C] ----
    const float inv0 = 1.0f / l0;
    const float inv1 = 1.0f / l1;
    const int b = bh >> 4, h = bh & 15;
    #pragma unroll
    for (int nt = 0; nt < 8; nt++) {
        const int coln = h * 64 + nt * 8 + tg * 2;
        float2 v0 = make_float2(oacc[nt][0] * inv0, oacc[nt][1] * inv0);
        float2 v1 = make_float2(oacc[nt][2] * inv1, oacc[nt][3] * inv1);
        *(float2*)&g_Y[((size_t)(b*TT + row0    ))*CC + coln] = v0;
        *(float2*)&g_Y[((size_t)(b*TT + row0 + 8))*CC + coln] = v1;
    }
}

// ---------------------------------------------------------------------------
extern "C" void kernel_launch(void* const* d_in, const int* in_sizes, int n_in,
                              void* d_out, int out_size)
{
    const float* x      = (const float*)d_in[0];
    const float* W_attn = (const float*)d_in[1];
    const float* b_attn = (const float*)d_in[2];
    const float* W_proj = (const float*)d_in[3];
    const float* b_proj = (const float*)d_in[4];
    float* out = (float*)d_out;

    static bool attr_set = false;
    if (!attr_set) {
        cudaFuncSetAttribute(attn3_kernel,
                             cudaFuncAttributeMaxDynamicSharedMemorySize, ATT_SMEM);
        cudaFuncSetAttribute(hgemm_kernel<0>,
                             cudaFuncAttributeMaxDynamicSharedMemorySize, GEMM_SMEM);
        cudaFuncSetAttribute(hgemm_kernel<1>,
                             cudaFuncAttributeMaxDynamicSharedMemorySize, GEMM_SMEM);
        attr_set = true;
    }

    // 1) QKV GEMM (tensor cores) + scatter into [B,H,T,D]
    hgemm_kernel<0><<<dim3(3*CC/128, MM/128), 256, GEMM_SMEM>>>(x, W_attn, b_attn, nullptr, 3*CC);
    // 2) Causal flash attention (tensor cores, FA2 layout)
    attn3_kernel<<<dim3(TT/128, BB*HH), 256, ATT_SMEM>>>();
    // 3) Output projection (tensor cores)
    hgemm_kernel<1><<<dim3(CC/128, MM/128), 256, GEMM_SMEM>>>(nullptr, W_proj, b_proj, out, CC);
}

// round 8
// speedup vs baseline: 3.3177x; 1.4022x over previous
#include <cuda_runtime.h>
#include <cuda_bf16.h>
#include <cstdint>

// Problem constants
#define BB 4
#define TT 2048
#define CC 1024
#define HH 16
#define DH 64
#define MM (BB*TT)          // 8192 rows for both GEMMs

// ---------------------------------------------------------------------------
// Pre-split bf16 hi/lo planes (device globals; uint4 for 16B alignment)
// ---------------------------------------------------------------------------
__device__ uint4 g_Xh4[MM*CC/8],  g_Xl4[MM*CC/8];          // x          [M][C]
__device__ uint4 g_Wh4[4*CC*CC/8], g_Wl4[4*CC*CC/8];       // W_attn|W_proj
__device__ uint4 g_Qh4[MM*CC/8],  g_Ql4[MM*CC/8];          // Q [B,H,T,D]
__device__ uint4 g_Kh4[MM*CC/8],  g_Kl4[MM*CC/8];
__device__ uint4 g_Vh4[MM*CC/8],  g_Vl4[MM*CC/8];
__device__ uint4 g_Yh4[MM*CC/8],  g_Yl4[MM*CC/8];          // attn out [B,T,C]

typedef __nv_bfloat16 bf16;

// ---------------------------------------------------------------------------
// primitives
// ---------------------------------------------------------------------------
__device__ __forceinline__ uint32_t smem_u32(const void* p) {
    return (uint32_t)__cvta_generic_to_shared(p);
}
__device__ __forceinline__ void ldsm4(uint32_t& r0, uint32_t& r1, uint32_t& r2, uint32_t& r3, uint32_t a) {
    asm volatile("ldmatrix.sync.aligned.m8n8.x4.shared.b16 {%0,%1,%2,%3},[%4];"
                 : "=r"(r0), "=r"(r1), "=r"(r2), "=r"(r3) : "r"(a));
}
__device__ __forceinline__ void ldsm4t(uint32_t& r0, uint32_t& r1, uint32_t& r2, uint32_t& r3, uint32_t a) {
    asm volatile("ldmatrix.sync.aligned.m8n8.x4.trans.shared.b16 {%0,%1,%2,%3},[%4];"
                 : "=r"(r0), "=r"(r1), "=r"(r2), "=r"(r3) : "r"(a));
}
__device__ __forceinline__ void mma16816(float* c, uint32_t a0, uint32_t a1, uint32_t a2, uint32_t a3,
                                         uint32_t b0, uint32_t b1) {
    asm volatile("mma.sync.aligned.m16n8k16.row.col.f32.bf16.bf16.f32 "
                 "{%0,%1,%2,%3},{%4,%5,%6,%7},{%8,%9},{%0,%1,%2,%3};"
                 : "+f"(c[0]), "+f"(c[1]), "+f"(c[2]), "+f"(c[3])
                 : "r"(a0), "r"(a1), "r"(a2), "r"(a3), "r"(b0), "r"(b1));
}
__device__ __forceinline__ uint32_t pack_bf16(float x, float y) {
    __nv_bfloat162 t = __floats2bfloat162_rn(x, y);
    return *(uint32_t*)&t;
}
__device__ __forceinline__ void splitf(float x, float& h, float& l) {
    h = __bfloat162float(__float2bfloat16(x));
    l = x - h;
}
__device__ __forceinline__ void split2(float x, float y, uint32_t& h, uint32_t& l) {
    float hx, lx, hy, ly;
    splitf(x, hx, lx); splitf(y, hy, ly);
    h = pack_bf16(hx, hy);
    l = pack_bf16(lx, ly);
}

// ---------------------------------------------------------------------------
// One-time split: x, W_attn, W_proj -> bf16 hi/lo planes.
// ---------------------------------------------------------------------------
__global__ void convert_kernel(const float* __restrict__ x,
                               const float* __restrict__ W_attn,
                               const float* __restrict__ W_proj)
{
    bf16* Xh = (bf16*)g_Xh4; bf16* Xl = (bf16*)g_Xl4;
    bf16* Wh = (bf16*)g_Wh4; bf16* Wl = (bf16*)g_Wl4;
    const int stride = gridDim.x * blockDim.x;
    const int t0 = blockIdx.x * blockDim.x + threadIdx.x;

    for (int i = t0; i < MM*CC/4; i += stride) {
        float4 v = *(const float4*)&x[(size_t)i*4];
        uint32_t h01, l01, h23, l23;
        split2(v.x, v.y, h01, l01);
        split2(v.z, v.w, h23, l23);
        *(uint2*)&Xh[(size_t)i*4] = make_uint2(h01, h23);
        *(uint2*)&Xl[(size_t)i*4] = make_uint2(l01, l23);
    }
    for (int i = t0; i < 3*CC*CC/4; i += stride) {
        float4 v = *(const float4*)&W_attn[(size_t)i*4];
        uint32_t h01, l01, h23, l23;
        split2(v.x, v.y, h01, l01);
        split2(v.z, v.w, h23, l23);
        *(uint2*)&Wh[(size_t)i*4] = make_uint2(h01, h23);
        *(uint2*)&Wl[(size_t)i*4] = make_uint2(l01, l23);
    }
    for (int i = t0; i < CC*CC/4; i += stride) {
        float4 v = *(const float4*)&W_proj[(size_t)i*4];
        uint32_t h01, l01, h23, l23;
        split2(v.x, v.y, h01, l01);
        split2(v.z, v.w, h23, l23);
        *(uint2*)&Wh[(size_t)(3*CC*CC) + (size_t)i*4] = make_uint2(h01, h23);
        *(uint2*)&Wl[(size_t)(3*CC*CC) + (size_t)i*4] = make_uint2(l01, l23);
    }
}

// ---------------------------------------------------------------------------
// Tensor-core GEMM, pre-split operands (pure copy load phase).
// Block 128x128x64, 256 threads, 8 warps (4m x 2n), warp tile 32x64.
// MODE 0: QKV (epilogue splits + scatters into Q/K/V hi/lo planes).
// MODE 1: proj (A = Y planes, write fp32 out).
// ---------------------------------------------------------------------------
#define GEMM_SMEM 65536

template<int MODE>
__global__ __launch_bounds__(256) void hgemm_kernel(const float* __restrict__ bias,
                                                    float* __restrict__ out,
                                                    int N)
{
    extern __shared__ char smg[];
    char* sAh = smg;
    char* sAl = smg + 16384;
    char* sBh = smg + 32768;
    char* sBl = smg + 49152;
    const uint32_t uAh = smem_u32(sAh), uAl = smem_u32(sAl);
    const uint32_t uBh = smem_u32(sBh), uBl = smem_u32(sBl);

    const bf16* Ah = (MODE == 0) ? (const bf16*)g_Xh4 : (const bf16*)g_Yh4;
    const bf16* Al = (MODE == 0) ? (const bf16*)g_Xl4 : (const bf16*)g_Yl4;
    const bf16* Wh = (const bf16*)g_Wh4 + (MODE == 0 ? 0 : (size_t)3*CC*CC);
    const bf16* Wl = (const bf16*)g_Wl4 + (MODE == 0 ? 0 : (size_t)3*CC*CC);

    const int bm = blockIdx.y * 128;
    const int bn = blockIdx.x * 128;
    const int tid  = threadIdx.x;
    const int wid  = tid >> 5;
    const int lane = tid & 31;
    const int warp_m = wid & 3;
    const int warp_n = wid >> 2;

    float acc[2][8][4];
    #pragma unroll
    for (int mt = 0; mt < 2; mt++)
        #pragma unroll
        for (int nt = 0; nt < 8; nt++)
            #pragma unroll
            for (int r = 0; r < 4; r++) acc[mt][nt][r] = 0.f;

    for (int k0 = 0; k0 < CC; k0 += 64) {
        // ---- A tile 128x64: 1024 16B-chunks per plane ----
        #pragma unroll
        for (int i = 0; i < 4; i++) {
            const int c  = i * 256 + tid;
            const int m  = c >> 3;
            const int k8 = c & 7;
            const size_t g = (size_t)(bm + m) * CC + k0 + k8 * 8;
            const int off = m * 128 + ((k8 ^ (m & 7)) << 4);
            *(uint4*)(sAh + off) = *(const uint4*)&Ah[g];
            *(uint4*)(sAl + off) = *(const uint4*)&Al[g];
        }
        // ---- B tile 64x128: 1024 16B-chunks per plane ----
        #pragma unroll
        for (int i = 0; i < 4; i++) {
            const int c  = i * 256 + tid;
            const int k  = c >> 4;
            const int n8 = c & 15;
            const size_t g = (size_t)(k0 + k) * N + bn + n8 * 8;
            const int off = k * 256 + ((n8 ^ (k & 7)) << 4);
            *(uint4*)(sBh + off) = *(const uint4*)&Wh[g];
            *(uint4*)(sBl + off) = *(const uint4*)&Wl[g];
        }
        __syncthreads();

        #pragma unroll
        for (int ks = 0; ks < 64; ks += 16) {
            uint32_t ah[2][4], al[2][4];
            #pragma unroll
            for (int mt = 0; mt < 2; mt++) {
                const int m = warp_m * 32 + mt * 16 + (lane & 15);
                const int k = ks + (lane >> 4) * 8;
                const uint32_t off = m * 128 + (((k >> 3) ^ (m & 7)) << 4);
                ldsm4(ah[mt][0], ah[mt][1], ah[mt][2], ah[mt][3], uAh + off);
                ldsm4(al[mt][0], al[mt][1], al[mt][2], al[mt][3], uAl + off);
            }
            uint32_t bh[8][2], bl[8][2];
            #pragma unroll
            for (int p = 0; p < 4; p++) {
                const int k = ks + ((lane >> 3) & 1) * 8 + (lane & 7);
                const int n = warp_n * 64 + p * 16 + (lane >> 4) * 8;
                const uint32_t off = k * 256 + (((n >> 3) ^ (k & 7)) << 4);
                ldsm4t(bh[2*p][0], bh[2*p][1], bh[2*p+1][0], bh[2*p+1][1], uBh + off);
                ldsm4t(bl[2*p][0], bl[2*p][1], bl[2*p+1][0], bl[2*p+1][1], uBl + off);
            }
            #pragma unroll
            for (int mt = 0; mt < 2; mt++)
                #pragma unroll
                for (int nt = 0; nt < 8; nt++) {
                    mma16816(acc[mt][nt], ah[mt][0], ah[mt][1], ah[mt][2], ah[mt][3],
                             bh[nt][0], bh[nt][1]);
                    mma16816(acc[mt][nt], ah[mt][0], ah[mt][1], ah[mt][2], ah[mt][3],
                             bl[nt][0], bl[nt][1]);
                    mma16816(acc[mt][nt], al[mt][0], al[mt][1], al[mt][2], al[mt][3],
                             bh[nt][0], bh[nt][1]);
                }
        }
        __syncthreads();
    }

    // ---- epilogue ----
    bf16* Qh = (bf16*)g_Qh4; bf16* Ql = (bf16*)g_Ql4;
    bf16* Kh = (bf16*)g_Kh4; bf16* Kl = (bf16*)g_Kl4;
    bf16* Vh = (bf16*)g_Vh4; bf16* Vl = (bf16*)g_Vl4;
    const int g  = lane >> 2;
    const int tg = lane & 3;
    #pragma unroll
    for (int mt = 0; mt < 2; mt++)
        #pragma unroll
        for (int nt = 0; nt < 8; nt++) {
            const int gn = bn + warp_n * 64 + nt * 8 + tg * 2;
            #pragma unroll
            for (int half = 0; half < 2; half++) {
                const int gm = bm + warp_m * 32 + mt * 16 + g + half * 8;
                const float v0 = acc[mt][nt][half * 2 + 0] + bias[gn];
                const float v1 = acc[mt][nt][half * 2 + 1] + bias[gn + 1];
                if (MODE == 0) {
                    uint32_t hp, lp;
                    split2(v0, v1, hp, lp);
                    const int which = gn >> 10;
                    const int c = gn & 1023;
                    const int h = c >> 6, d = c & 63;     // d even
                    const int b = gm >> 11;
                    const int t = gm & 2047;
                    const size_t idx = ((size_t)((b*HH + h)*TT + t))*DH + d;
                    if (which == 0)      { *(uint32_t*)&Qh[idx] = hp; *(uint32_t*)&Ql[idx] = lp; }
                    else if (which == 1) { *(uint32_t*)&Kh[idx] = hp; *(uint32_t*)&Kl[idx] = lp; }
                    else                 { *(uint32_t*)&Vh[idx] = hp; *(uint32_t*)&Vl[idx] = lp; }
                } else {
                    out[(size_t)gm * N + gn    ] = v0;
                    out[(size_t)gm * N + gn + 1] = v1;
                }
            }
        }
}

// ---------------------------------------------------------------------------
// Flash attention (tensor-core, FA2 layout), pre-split K/V/Q planes.
// Block = 8 warps, 128 queries of one (b,h). Key tiles of 64.
// Smem (32KB): phase 1 = Q hi/lo stage; then Kh/Kl/Vh/Vl 8KB each.
// ---------------------------------------------------------------------------
#define ATT_SMEM 32768

__global__ __launch_bounds__(256) void attn3_kernel()
{
    extern __shared__ char smx[];
    const uint32_t uB = smem_u32(smx);

    const int bh  = blockIdx.y;
    const int qtb = blockIdx.x;
    const int qb  = qtb * 128;
    const int tid = threadIdx.x;
    const int wid = tid >> 5;
    const int lane = tid & 31;

    const bf16* Qh = (const bf16*)g_Qh4 + (size_t)bh * TT * DH;
    const bf16* Ql = (const bf16*)g_Ql4 + (size_t)bh * TT * DH;
    const bf16* Kh = (const bf16*)g_Kh4 + (size_t)bh * TT * DH;
    const bf16* Kl = (const bf16*)g_Kl4 + (size_t)bh * TT * DH;
    const bf16* Vh = (const bf16*)g_Vh4 + (size_t)bh * TT * DH;
    const bf16* Vl = (const bf16*)g_Vl4 + (size_t)bh * TT * DH;

    // ---- stage Q tile (pure copy, swizzled) ----
    #pragma unroll
    for (int i = 0; i < 4; i++) {
        const int c  = i * 256 + tid;          // 1024 chunks per plane
        const int m  = c >> 3;
        const int d8 = c & 7;
        const size_t g = (size_t)(qb + m) * DH + d8 * 8;
        const int off = m * 128 + ((d8 ^ (m & 7)) << 4);
        *(uint4*)(smx + off)         = *(const uint4*)&Qh[g];
        *(uint4*)(smx + 16384 + off) = *(const uint4*)&Ql[g];
    }
    __syncthreads();

    uint32_t qh[4][4], ql[4][4];
    {
        const int m = wid * 16 + (lane & 15);
        #pragma unroll
        for (int ks = 0; ks < 4; ks++) {
            const int k = ks * 16 + (lane >> 4) * 8;
            const uint32_t off = m * 128 + (((k >> 3) ^ (m & 7)) << 4);
            ldsm4(qh[ks][0], qh[ks][1], qh[ks][2], qh[ks][3], uB + off);
            ldsm4(ql[ks][0], ql[ks][1], ql[ks][2], ql[ks][3], uB + 16384 + off);
        }
    }
    __syncthreads();

    float oacc[8][4];
    #pragma unroll
    for (int nt = 0; nt < 8; nt++)
        #pragma unroll
        for (int r = 0; r < 4; r++) oacc[nt][r] = 0.f;
    float m0 = -1e30f, m1 = -1e30f, l0 = 0.f, l1 = 0.f;

    const int qw = qb + wid * 16;
    const int g  = lane >> 2;
    const int tg = lane & 3;
    const int row0 = qw + g;
    const float scale = 0.125f;
    const int ktmax = 2 * qtb + 1;

    for (int kt = 0; kt <= ktmax; kt++) {
        // ---- copy K/V hi/lo tiles (512 chunks per plane) ----
        #pragma unroll
        for (int i = 0; i < 2; i++) {
            const int c  = i * 256 + tid;
            const int r  = c >> 3;
            const int d8 = c & 7;
            const size_t gg = (size_t)(kt*64 + r) * DH + d8 * 8;
            const int off = r * 128 + ((d8 ^ (r & 7)) << 4);
            *(uint4*)(smx + off)         = *(const uint4*)&Kh[gg];
            *(uint4*)(smx + 8192 + off)  = *(const uint4*)&Kl[gg];
            *(uint4*)(smx + 16384 + off) = *(const uint4*)&Vh[gg];
            *(uint4*)(smx + 24576 + off) = *(const uint4*)&Vl[gg];
        }
        __syncthreads();

        if (kt * 64 <= qw + 15) {
            // ---- S = Q K^T ----
            float sacc[8][4];
            #pragma unroll
            for (int nt = 0; nt < 8; nt++)
                #pragma unroll
                for (int r = 0; r < 4; r++) sacc[nt][r] = 0.f;

            #pragma unroll
            for (int ks = 0; ks < 4; ks++) {
                #pragma unroll
                for (int p = 0; p < 4; p++) {
                    const int n = p * 16 + (lane & 15);
                    const int k = ks * 16 + (lane >> 4) * 8;
                    const uint32_t off = n * 128 + (((k >> 3) ^ (n & 7)) << 4);
                    uint32_t b0a, b0b, b1a, b1b;
                    ldsm4(b0a, b0b, b1a, b1b, uB + off);          // Kh
                    mma16816(sacc[2*p  ], qh[ks][0], qh[ks][1], qh[ks][2], qh[ks][3], b0a, b1a);
                    mma16816(sacc[2*p+1], qh[ks][0], qh[ks][1], qh[ks][2], qh[ks][3], b0b, b1b);
                    mma16816(sacc[2*p  ], ql[ks][0], ql[ks][1], ql[ks][2], ql[ks][3], b0a, b1a);
                    mma16816(sacc[2*p+1], ql[ks][0], ql[ks][1], ql[ks][2], ql[ks][3], b0b, b1b);
                    ldsm4(b0a, b0b, b1a, b1b, uB + 8192 + off);   // Kl
                    mma16816(sacc[2*p  ], qh[ks][0], qh[ks][1], qh[ks][2], qh[ks][3], b0a, b1a);
                    mma16816(sacc[2*p+1], qh[ks][0], qh[ks][1], qh[ks][2], qh[ks][3], b0b, b1b);
                }
            }

            // ---- scale + causal mask ----
            if (kt * 64 + 63 > qw) {
                #pragma unroll
                for (int nt = 0; nt < 8; nt++) {
                    const int col = kt * 64 + nt * 8 + tg * 2;
                    sacc[nt][0] = (col     <= row0    ) ? sacc[nt][0] * scale : -1e30f;
                    sacc[nt][1] = (col + 1 <= row0    ) ? sacc[nt][1] * scale : -1e30f;
                    sacc[nt][2] = (col     <= row0 + 8) ? sacc[nt][2] * scale : -1e30f;
                    sacc[nt][3] = (col + 1 <= row0 + 8) ? sacc[nt][3] * scale : -1e30f;
                }
            } else {
                #pragma unroll
                for (int nt = 0; nt < 8; nt++)
                    #pragma unroll
                    for (int r = 0; r < 4; r++) sacc[nt][r] *= scale;
            }

            // ---- online softmax ----
            float mx0 = -1e30f, mx1 = -1e30f;
            #pragma unroll
            for (int nt = 0; nt < 8; nt++) {
                mx0 = fmaxf(mx0, fmaxf(sacc[nt][0], sacc[nt][1]));
                mx1 = fmaxf(mx1, fmaxf(sacc[nt][2], sacc[nt][3]));
            }
            mx0 = fmaxf(mx0, __shfl_xor_sync(0xffffffffu, mx0, 1));
            mx0 = fmaxf(mx0, __shfl_xor_sync(0xffffffffu, mx0, 2));
            mx1 = fmaxf(mx1, __shfl_xor_sync(0xffffffffu, mx1, 1));
            mx1 = fmaxf(mx1, __shfl_xor_sync(0xffffffffu, mx1, 2));
            const float mn0 = fmaxf(m0, mx0);
            const float mn1 = fmaxf(m1, mx1);
            const float corr0 = __expf(m0 - mn0);
            const float corr1 = __expf(m1 - mn1);

            uint32_t ph01[8], ph23[8], pl01[8], pl23[8];
            float ps0 = 0.f, ps1 = 0.f;
            #pragma unroll
            for (int nt = 0; nt < 8; nt++) {
                const float p0 = __expf(sacc[nt][0] - mn0);
                const float p1 = __expf(sacc[nt][1] - mn0);
                const float p2 = __expf(sacc[nt][2] - mn1);
                const float p3 = __expf(sacc[nt][3] - mn1);
                ps0 += p0 + p1;
                ps1 += p2 + p3;
                split2(p0, p1, ph01[nt], pl01[nt]);
                split2(p2, p3, ph23[nt], pl23[nt]);
            }
            ps0 += __shfl_xor_sync(0xffffffffu, ps0, 1);
            ps0 += __shfl_xor_sync(0xffffffffu, ps0, 2);
            ps1 += __shfl_xor_sync(0xffffffffu, ps1, 1);
            ps1 += __shfl_xor_sync(0xffffffffu, ps1, 2);
            l0 = l0 * corr0 + ps0;  m0 = mn0;
            l1 = l1 * corr1 + ps1;  m1 = mn1;
            #pragma unroll
            for (int nt = 0; nt < 8; nt++) {
                oacc[nt][0] *= corr0; oacc[nt][1] *= corr0;
                oacc[nt][2] *= corr1; oacc[nt][3] *= corr1;
            }

            // ---- O += P V ----
            #pragma unroll
            for (int kk = 0; kk < 4; kk++) {
                const uint32_t a0 = ph01[2*kk],   a1 = ph23[2*kk];
                const uint32_t a2 = ph01[2*kk+1], a3 = ph23[2*kk+1];
                const uint32_t c0 = pl01[2*kk],   c1 = pl23[2*kk];
                const uint32_t c2 = pl01[2*kk+1], c3 = pl23[2*kk+1];
                #pragma unroll
                for (int dp = 0; dp < 4; dp++) {
                    const int r = kk * 16 + (lane & 15);
                    const int d = dp * 16 + (lane >> 4) * 8;
                    const uint32_t off = r * 128 + (((d >> 3) ^ (r & 7)) << 4);
                    uint32_t b0a, b1a, b0b, b1b;
                    ldsm4t(b0a, b1a, b0b, b1b, uB + 16384 + off);   // Vh
                    mma16816(oacc[2*dp  ], a0, a1, a2, a3, b0a, b1a);
                    mma16816(oacc[2*dp+1], a0, a1, a2, a3, b0b, b1b);
                    mma16816(oacc[2*dp  ], c0, c1, c2, c3, b0a, b1a);
                    mma16816(oacc[2*dp+1], c0, c1, c2, c3, b0b, b1b);
                    ldsm4t(b0a, b1a, b0b, b1b, uB + 24576 + off);   // Vl
                    mma16816(oacc[2*dp  ], a0, a1, a2, a3, b0a, b1a);
                    mma16816(oacc[2*dp+1], a0, a1, a2, a3, b0b, b1b);
                }
            }
        }
        __syncthreads();
    }

    // ---- epilogue: normalize, split, write Y hi/lo planes [B,T,C] ----
    bf16* Yh = (bf16*)g_Yh4;
    bf16* Yl = (bf16*)g_Yl4;
    const float inv0 = 1.0f / l0;
    const float inv1 = 1.0f / l1;
    const int b = bh >> 4, h = bh & 15;
    #pragma unroll
    for (int nt = 0; nt < 8; nt++) {
        const int coln = h * 64 + nt * 8 + tg * 2;
        uint32_t hp, lp;
        split2(oacc[nt][0] * inv0, oacc[nt][1] * inv0, hp, lp);
        *(uint32_t*)&Yh[((size_t)(b*TT + row0))*CC + coln] = hp;
        *(uint32_t*)&Yl[((size_t)(b*TT + row0))*CC + coln] = lp;
        split2(oacc[nt][2] * inv1, oacc[nt][3] * inv1, hp, lp);
        *(uint32_t*)&Yh[((size_t)(b*TT + row0 + 8))*CC + coln] = hp;
        *(uint32_t*)&Yl[((size_t)(b*TT + row0 + 8))*CC + coln] = lp;
    }
}

// ---------------------------------------------------------------------------
extern "C" void kernel_launch(void* const* d_in, const int* in_sizes, int n_in,
                              void* d_out, int out_size)
{
    const float* x      = (const float*)d_in[0];
    const float* b_attn = (const float*)d_in[2];
    const float* b_proj = (const float*)d_in[4];
    float* out = (float*)d_out;

    static bool attr_set = false;
    if (!attr_set) {
        cudaFuncSetAttribute(attn3_kernel,
                             cudaFuncAttributeMaxDynamicSharedMemorySize, ATT_SMEM);
        cudaFuncSetAttribute(hgemm_kernel<0>,
                             cudaFuncAttributeMaxDynamicSharedMemorySize, GEMM_SMEM);
        cudaFuncSetAttribute(hgemm_kernel<1>,
                             cudaFuncAttributeMaxDynamicSharedMemorySize, GEMM_SMEM);
        attr_set = true;
    }

    // 0) one-time fp32 -> bf16 hi/lo split of x and weights
    convert_kernel<<<1024, 256>>>(x, (const float*)d_in[1], (const float*)d_in[3]);
    // 1) QKV GEMM (pre-split operands) + split-scatter into Q/K/V planes
    hgemm_kernel<0><<<dim3(3*CC/128, MM/128), 256, GEMM_SMEM>>>(b_attn, nullptr, 3*CC);
    // 2) Causal flash attention (tensor cores, pre-split K/V)
    attn3_kernel<<<dim3(TT/128, BB*HH), 256, ATT_SMEM>>>();
    // 3) Output projection
    hgemm_kernel<1><<<dim3(CC/128, MM/128), 256, GEMM_SMEM>>>(b_proj, out, CC);
}

// round 9
// speedup vs baseline: 4.1508x; 1.2511x over previous
#include <cuda_runtime.h>
#include <cuda_bf16.h>
#include <cstdint>

// Problem constants
#define BB 4
#define TT 2048
#define CC 1024
#define HH 16
#define DH 64
#define MM (BB*TT)          // 8192 rows for both GEMMs

// ---------------------------------------------------------------------------
// Pre-split bf16 hi/lo planes (device globals; uint4 for 16B alignment)
// ---------------------------------------------------------------------------
__device__ uint4 g_Xh4[MM*CC/8],  g_Xl4[MM*CC/8];          // x          [M][C]
__device__ uint4 g_Wh4[4*CC*CC/8], g_Wl4[4*CC*CC/8];       // W_attn|W_proj
__device__ uint4 g_Qh4[MM*CC/8],  g_Ql4[MM*CC/8];          // Q [B,H,T,D]
__device__ uint4 g_Kh4[MM*CC/8],  g_Kl4[MM*CC/8];
__device__ uint4 g_Vh4[MM*CC/8],  g_Vl4[MM*CC/8];
__device__ uint4 g_Yh4[MM*CC/8],  g_Yl4[MM*CC/8];          // attn out [B,T,C]

typedef __nv_bfloat16 bf16;

// ---------------------------------------------------------------------------
// primitives
// ---------------------------------------------------------------------------
__device__ __forceinline__ uint32_t smem_u32(const void* p) {
    return (uint32_t)__cvta_generic_to_shared(p);
}
__device__ __forceinline__ void ldsm4(uint32_t& r0, uint32_t& r1, uint32_t& r2, uint32_t& r3, uint32_t a) {
    asm volatile("ldmatrix.sync.aligned.m8n8.x4.shared.b16 {%0,%1,%2,%3},[%4];"
                 : "=r"(r0), "=r"(r1), "=r"(r2), "=r"(r3) : "r"(a));
}
__device__ __forceinline__ void ldsm4t(uint32_t& r0, uint32_t& r1, uint32_t& r2, uint32_t& r3, uint32_t a) {
    asm volatile("ldmatrix.sync.aligned.m8n8.x4.trans.shared.b16 {%0,%1,%2,%3},[%4];"
                 : "=r"(r0), "=r"(r1), "=r"(r2), "=r"(r3) : "r"(a));
}
__device__ __forceinline__ void mma16816(float* c, uint32_t a0, uint32_t a1, uint32_t a2, uint32_t a3,
                                         uint32_t b0, uint32_t b1) {
    asm volatile("mma.sync.aligned.m16n8k16.row.col.f32.bf16.bf16.f32 "
                 "{%0,%1,%2,%3},{%4,%5,%6,%7},{%8,%9},{%0,%1,%2,%3};"
                 : "+f"(c[0]), "+f"(c[1]), "+f"(c[2]), "+f"(c[3])
                 : "r"(a0), "r"(a1), "r"(a2), "r"(a3), "r"(b0), "r"(b1));
}
__device__ __forceinline__ void cp16(uint32_t s, const void* g) {
    asm volatile("cp.async.cg.shared.global [%0], [%1], 16;" :: "r"(s), "l"(g));
}
__device__ __forceinline__ void cp_commit() {
    asm volatile("cp.async.commit_group;" ::: "memory");
}
__device__ __forceinline__ void cp_wait0() {
    asm volatile("cp.async.wait_group 0;" ::: "memory");
}
__device__ __forceinline__ uint32_t pack_bf16(float x, float y) {
    __nv_bfloat162 t = __floats2bfloat162_rn(x, y);
    return *(uint32_t*)&t;
}
__device__ __forceinline__ void splitf(float x, float& h, float& l) {
    h = __bfloat162float(__float2bfloat16(x));
    l = x - h;
}
__device__ __forceinline__ void split2(float x, float y, uint32_t& h, uint32_t& l) {
    float hx, lx, hy, ly;
    splitf(x, hx, lx); splitf(y, hy, ly);
    h = pack_bf16(hx, hy);
    l = pack_bf16(lx, ly);
}

// ---------------------------------------------------------------------------
// One-time split: x, W_attn, W_proj -> bf16 hi/lo planes.
// ---------------------------------------------------------------------------
__global__ void convert_kernel(const float* __restrict__ x,
                               const float* __restrict__ W_attn,
                               const float* __restrict__ W_proj)
{
    bf16* Xh = (bf16*)g_Xh4; bf16* Xl = (bf16*)g_Xl4;
    bf16* Wh = (bf16*)g_Wh4; bf16* Wl = (bf16*)g_Wl4;
    const int stride = gridDim.x * blockDim.x;
    const int t0 = blockIdx.x * blockDim.x + threadIdx.x;

    for (int i = t0; i < MM*CC/4; i += stride) {
        float4 v = *(const float4*)&x[(size_t)i*4];
        uint32_t h01, l01, h23, l23;
        split2(v.x, v.y, h01, l01);
        split2(v.z, v.w, h23, l23);
        *(uint2*)&Xh[(size_t)i*4] = make_uint2(h01, h23);
        *(uint2*)&Xl[(size_t)i*4] = make_uint2(l01, l23);
    }
    for (int i = t0; i < 3*CC*CC/4; i += stride) {
        float4 v = *(const float4*)&W_attn[(size_t)i*4];
        uint32_t h01, l01, h23, l23;
        split2(v.x, v.y, h01, l01);
        split2(v.z, v.w, h23, l23);
        *(uint2*)&Wh[(size_t)i*4] = make_uint2(h01, h23);
        *(uint2*)&Wl[(size_t)i*4] = make_uint2(l01, l23);
    }
    for (int i = t0; i < CC*CC/4; i += stride) {
        float4 v = *(const float4*)&W_proj[(size_t)i*4];
        uint32_t h01, l01, h23, l23;
        split2(v.x, v.y, h01, l01);
        split2(v.z, v.w, h23, l23);
        *(uint2*)&Wh[(size_t)(3*CC*CC) + (size_t)i*4] = make_uint2(h01, h23);
        *(uint2*)&Wl[(size_t)(3*CC*CC) + (size_t)i*4] = make_uint2(l01, l23);
    }
}

// ---------------------------------------------------------------------------
// Tensor-core GEMM, pre-split operands, cp.async double-buffered.
// Block 128x128x64, 256 threads, 8 warps (4m x 2n), warp tile 32x64.
// Smem: 2 stages x 64KB (sAh/sAl/sBh/sBl 16KB each).
// ---------------------------------------------------------------------------
#define GEMM_STAGE 65536
#define GEMM_SMEM  (2*GEMM_STAGE)

template<int MODE>
__device__ __forceinline__ void gemm_load_tile(uint32_t uS, const bf16* Ah, const bf16* Al,
                                               const bf16* Wh, const bf16* Wl,
                                               int bm, int bn, int k0, int N, int tid)
{
    #pragma unroll
    for (int i = 0; i < 4; i++) {
        const int c  = i * 256 + tid;
        const int m  = c >> 3;
        const int k8 = c & 7;
        const size_t g = (size_t)(bm + m) * CC + k0 + k8 * 8;
        const uint32_t off = m * 128 + ((k8 ^ (m & 7)) << 4);
        cp16(uS + off,         &Ah[g]);
        cp16(uS + 16384 + off, &Al[g]);
    }
    #pragma unroll
    for (int i = 0; i < 4; i++) {
        const int c  = i * 256 + tid;
        const int k  = c >> 4;
        const int n8 = c & 15;
        const size_t g = (size_t)(k0 + k) * N + bn + n8 * 8;
        const uint32_t off = k * 256 + ((n8 ^ (k & 7)) << 4);
        cp16(uS + 32768 + off, &Wh[g]);
        cp16(uS + 49152 + off, &Wl[g]);
    }
}

template<int MODE>
__global__ __launch_bounds__(256) void hgemm_kernel(const float* __restrict__ bias,
                                                    float* __restrict__ out,
                                                    int N)
{
    extern __shared__ char smg[];
    const uint32_t uBase = smem_u32(smg);

    const bf16* Ah = (MODE == 0) ? (const bf16*)g_Xh4 : (const bf16*)g_Yh4;
    const bf16* Al = (MODE == 0) ? (const bf16*)g_Xl4 : (const bf16*)g_Yl4;
    const bf16* Wh = (const bf16*)g_Wh4 + (MODE == 0 ? 0 : (size_t)3*CC*CC);
    const bf16* Wl = (const bf16*)g_Wl4 + (MODE == 0 ? 0 : (size_t)3*CC*CC);

    const int bm = blockIdx.y * 128;
    const int bn = blockIdx.x * 128;
    const int tid  = threadIdx.x;
    const int wid  = tid >> 5;
    const int lane = tid & 31;
    const int warp_m = wid & 3;
    const int warp_n = wid >> 2;

    float acc[2][8][4];
    #pragma unroll
    for (int mt = 0; mt < 2; mt++)
        #pragma unroll
        for (int nt = 0; nt < 8; nt++)
            #pragma unroll
            for (int r = 0; r < 4; r++) acc[mt][nt][r] = 0.f;

    // prologue: stage 0
    gemm_load_tile<MODE>(uBase, Ah, Al, Wh, Wl, bm, bn, 0, N, tid);
    cp_commit();

    const int NT = CC / 64;    // 16
    for (int kt = 0; kt < NT; kt++) {
        cp_wait0();
        __syncthreads();
        if (kt + 1 < NT) {
            gemm_load_tile<MODE>(uBase + ((kt + 1) & 1) * GEMM_STAGE,
                                 Ah, Al, Wh, Wl, bm, bn, (kt + 1) * 64, N, tid);
            cp_commit();
        }
        const uint32_t uAh = uBase + (kt & 1) * GEMM_STAGE;
        const uint32_t uAl = uAh + 16384;
        const uint32_t uBh = uAh + 32768;
        const uint32_t uBl = uAh + 49152;

        #pragma unroll
        for (int ks = 0; ks < 64; ks += 16) {
            uint32_t ah[2][4], al[2][4];
            #pragma unroll
            for (int mt = 0; mt < 2; mt++) {
                const int m = warp_m * 32 + mt * 16 + (lane & 15);
                const int k = ks + (lane >> 4) * 8;
                const uint32_t off = m * 128 + (((k >> 3) ^ (m & 7)) << 4);
                ldsm4(ah[mt][0], ah[mt][1], ah[mt][2], ah[mt][3], uAh + off);
                ldsm4(al[mt][0], al[mt][1], al[mt][2], al[mt][3], uAl + off);
            }
            uint32_t bh[8][2], bl[8][2];
            #pragma unroll
            for (int p = 0; p < 4; p++) {
                const int k = ks + ((lane >> 3) & 1) * 8 + (lane & 7);
                const int n = warp_n * 64 + p * 16 + (lane >> 4) * 8;
                const uint32_t off = k * 256 + (((n >> 3) ^ (k & 7)) << 4);
                ldsm4t(bh[2*p][0], bh[2*p][1], bh[2*p+1][0], bh[2*p+1][1], uBh + off);
                ldsm4t(bl[2*p][0], bl[2*p][1], bl[2*p+1][0], bl[2*p+1][1], uBl + off);
            }
            #pragma unroll
            for (int mt = 0; mt < 2; mt++)
                #pragma unroll
                for (int nt = 0; nt < 8; nt++) {
                    mma16816(acc[mt][nt], ah[mt][0], ah[mt][1], ah[mt][2], ah[mt][3],
                             bh[nt][0], bh[nt][1]);
                    mma16816(acc[mt][nt], ah[mt][0], ah[mt][1], ah[mt][2], ah[mt][3],
                             bl[nt][0], bl[nt][1]);
                    mma16816(acc[mt][nt], al[mt][0], al[mt][1], al[mt][2], al[mt][3],
                             bh[nt][0], bh[nt][1]);
                }
        }
        __syncthreads();
    }

    // ---- epilogue ----
    bf16* Qh = (bf16*)g_Qh4; bf16* Ql = (bf16*)g_Ql4;
    bf16* Kh = (bf16*)g_Kh4; bf16* Kl = (bf16*)g_Kl4;
    bf16* Vh = (bf16*)g_Vh4; bf16* Vl = (bf16*)g_Vl4;
    const int g  = lane >> 2;
    const int tg = lane & 3;
    #pragma unroll
    for (int mt = 0; mt < 2; mt++)
        #pragma unroll
        for (int nt = 0; nt < 8; nt++) {
            const int gn = bn + warp_n * 64 + nt * 8 + tg * 2;
            #pragma unroll
            for (int half = 0; half < 2; half++) {
                const int gm = bm + warp_m * 32 + mt * 16 + g + half * 8;
                const float v0 = acc[mt][nt][half * 2 + 0] + bias[gn];
                const float v1 = acc[mt][nt][half * 2 + 1] + bias[gn + 1];
                if (MODE == 0) {
                    uint32_t hp, lp;
                    split2(v0, v1, hp, lp);
                    const int which = gn >> 10;
                    const int c = gn & 1023;
                    const int h = c >> 6, d = c & 63;
                    const int b = gm >> 11;
                    const int t = gm & 2047;
                    const size_t idx = ((size_t)((b*HH + h)*TT + t))*DH + d;
                    if (which == 0)      { *(uint32_t*)&Qh[idx] = hp; *(uint32_t*)&Ql[idx] = lp; }
                    else if (which == 1) { *(uint32_t*)&Kh[idx] = hp; *(uint32_t*)&Kl[idx] = lp; }
                    else                 { *(uint32_t*)&Vh[idx] = hp; *(uint32_t*)&Vl[idx] = lp; }
                } else {
                    out[(size_t)gm * N + gn    ] = v0;
                    out[(size_t)gm * N + gn + 1] = v1;
                }
            }
        }
}

// ---------------------------------------------------------------------------
// Flash attention (tensor-core, FA2 layout), pre-split planes,
// cp.async double-buffered K/V tiles (2 stages x 32KB).
// ---------------------------------------------------------------------------
#define ATT_STAGE 32768
#define ATT_SMEM  (2*ATT_STAGE)

__device__ __forceinline__ void attn_load_tile(uint32_t uS,
                                               const bf16* Kh, const bf16* Kl,
                                               const bf16* Vh, const bf16* Vl,
                                               int kt, int tid)
{
    #pragma unroll
    for (int i = 0; i < 2; i++) {
        const int c  = i * 256 + tid;
        const int r  = c >> 3;
        const int d8 = c & 7;
        const size_t gg = (size_t)(kt*64 + r) * DH + d8 * 8;
        const uint32_t off = r * 128 + ((d8 ^ (r & 7)) << 4);
        cp16(uS + off,         &Kh[gg]);
        cp16(uS + 8192 + off,  &Kl[gg]);
        cp16(uS + 16384 + off, &Vh[gg]);
        cp16(uS + 24576 + off, &Vl[gg]);
    }
}

__global__ __launch_bounds__(256) void attn3_kernel()
{
    extern __shared__ char smx[];
    const uint32_t uB = smem_u32(smx);

    const int bh  = blockIdx.y;
    const int qtb = blockIdx.x;
    const int qb  = qtb * 128;
    const int tid = threadIdx.x;
    const int wid = tid >> 5;
    const int lane = tid & 31;

    const bf16* Qh = (const bf16*)g_Qh4 + (size_t)bh * TT * DH;
    const bf16* Ql = (const bf16*)g_Ql4 + (size_t)bh * TT * DH;
    const bf16* Kh = (const bf16*)g_Kh4 + (size_t)bh * TT * DH;
    const bf16* Kl = (const bf16*)g_Kl4 + (size_t)bh * TT * DH;
    const bf16* Vh = (const bf16*)g_Vh4 + (size_t)bh * TT * DH;
    const bf16* Vl = (const bf16*)g_Vl4 + (size_t)bh * TT * DH;

    // ---- stage Q tile (pure copy, swizzled) ----
    #pragma unroll
    for (int i = 0; i < 4; i++) {
        const int c  = i * 256 + tid;
        const int m  = c >> 3;
        const int d8 = c & 7;
        const size_t g = (size_t)(qb + m) * DH + d8 * 8;
        const uint32_t off = m * 128 + ((d8 ^ (m & 7)) << 4);
        *(uint4*)(smx + off)         = *(const uint4*)&Qh[g];
        *(uint4*)(smx + 16384 + off) = *(const uint4*)&Ql[g];
    }
    __syncthreads();

    uint32_t qh[4][4], ql[4][4];
    {
        const int m = wid * 16 + (lane & 15);
        #pragma unroll
        for (int ks = 0; ks < 4; ks++) {
            const int k = ks * 16 + (lane >> 4) * 8;
            const uint32_t off = m * 128 + (((k >> 3) ^ (m & 7)) << 4);
            ldsm4(qh[ks][0], qh[ks][1], qh[ks][2], qh[ks][3], uB + off);
            ldsm4(ql[ks][0], ql[ks][1], ql[ks][2], ql[ks][3], uB + 16384 + off);
        }
    }
    __syncthreads();   // Q smem region free; stage 0 overlaps it

    float oacc[8][4];
    #pragma unroll
    for (int nt = 0; nt < 8; nt++)
        #pragma unroll
        for (int r = 0; r < 4; r++) oacc[nt][r] = 0.f;
    float m0 = -1e30f, m1 = -1e30f, l0 = 0.f, l1 = 0.f;

    const int qw = qb + wid * 16;
    const int g  = lane >> 2;
    const int tg = lane & 3;
    const int row0 = qw + g;
    const float scale = 0.125f;
    const int ktmax = 2 * qtb + 1;

    // prologue
    attn_load_tile(uB, Kh, Kl, Vh, Vl, 0, tid);
    cp_commit();

    for (int kt = 0; kt <= ktmax; kt++) {
        cp_wait0();
        __syncthreads();
        if (kt + 1 <= ktmax) {
            attn_load_tile(uB + ((kt + 1) & 1) * ATT_STAGE, Kh, Kl, Vh, Vl, kt + 1, tid);
            cp_commit();
        }
        const uint32_t uS = uB + (kt & 1) * ATT_STAGE;

        if (kt * 64 <= qw + 15) {
            // ---- S = Q K^T ----
            float sacc[8][4];
            #pragma unroll
            for (int nt = 0; nt < 8; nt++)
                #pragma unroll
                for (int r = 0; r < 4; r++) sacc[nt][r] = 0.f;

            #pragma unroll
            for (int ks = 0; ks < 4; ks++) {
                #pragma unroll
                for (int p = 0; p < 4; p++) {
                    const int n = p * 16 + (lane & 15);
                    const int k = ks * 16 + (lane >> 4) * 8;
                    const uint32_t off = n * 128 + (((k >> 3) ^ (n & 7)) << 4);
                    uint32_t b0a, b0b, b1a, b1b;
                    ldsm4(b0a, b0b, b1a, b1b, uS + off);          // Kh
                    mma16816(sacc[2*p  ], qh[ks][0], qh[ks][1], qh[ks][2], qh[ks][3], b0a, b1a);
                    mma16816(sacc[2*p+1], qh[ks][0], qh[ks][1], qh[ks][2], qh[ks][3], b0b, b1b);
                    mma16816(sacc[2*p  ], ql[ks][0], ql[ks][1], ql[ks][2], ql[ks][3], b0a, b1a);
                    mma16816(sacc[2*p+1], ql[ks][0], ql[ks][1], ql[ks][2], ql[ks][3], b0b, b1b);
                    ldsm4(b0a, b0b, b1a, b1b, uS + 8192 + off);   // Kl
                    mma16816(sacc[2*p  ], qh[ks][0], qh[ks][1], qh[ks][2], qh[ks][3], b0a, b1a);
                    mma16816(sacc[2*p+1], qh[ks][0], qh[ks][1], qh[ks][2], qh[ks][3], b0b, b1b);
                }
            }

            // ---- scale + causal mask ----
            if (kt * 64 + 63 > qw) {
                #pragma unroll
                for (int nt = 0; nt < 8; nt++) {
                    const int col = kt * 64 + nt * 8 + tg * 2;
                    sacc[nt][0] = (col     <= row0    ) ? sacc[nt][0] * scale : -1e30f;
                    sacc[nt][1] = (col + 1 <= row0    ) ? sacc[nt][1] * scale : -1e30f;
                    sacc[nt][2] = (col     <= row0 + 8) ? sacc[nt][2] * scale : -1e30f;
                    sacc[nt][3] = (col + 1 <= row0 + 8) ? sacc[nt][3] * scale : -1e30f;
                }
            } else {
                #pragma unroll
                for (int nt = 0; nt < 8; nt++)
                    #pragma unroll
                    for (int r = 0; r < 4; r++) sacc[nt][r] *= scale;
            }

            // ---- online softmax ----
            float mx0 = -1e30f, mx1 = -1e30f;
            #pragma unroll
            for (int nt = 0; nt < 8; nt++) {
                mx0 = fmaxf(mx0, fmaxf(sacc[nt][0], sacc[nt][1]));
                mx1 = fmaxf(mx1, fmaxf(sacc[nt][2], sacc[nt][3]));
            }
            mx0 = fmaxf(mx0, __shfl_xor_sync(0xffffffffu, mx0, 1));
            mx0 = fmaxf(mx0, __shfl_xor_sync(0xffffffffu, mx0, 2));
            mx1 = fmaxf(mx1, __shfl_xor_sync(0xffffffffu, mx1, 1));
            mx1 = fmaxf(mx1, __shfl_xor_sync(0xffffffffu, mx1, 2));
            const float mn0 = fmaxf(m0, mx0);
            const float mn1 = fmaxf(m1, mx1);
            const float corr0 = __expf(m0 - mn0);
            const float corr1 = __expf(m1 - mn1);

            uint32_t ph01[8], ph23[8], pl01[8], pl23[8];
            float ps0 = 0.f, ps1 = 0.f;
            #pragma unroll
            for (int nt = 0; nt < 8; nt++) {
                const float p0 = __expf(sacc[nt][0] - mn0);
                const float p1 = __expf(sacc[nt][1] - mn0);
                const float p2 = __expf(sacc[nt][2] - mn1);
                const float p3 = __expf(sacc[nt][3] - mn1);
                ps0 += p0 + p1;
                ps1 += p2 + p3;
                split2(p0, p1, ph01[nt], pl01[nt]);
                split2(p2, p3, ph23[nt], pl23[nt]);
            }
            ps0 += __shfl_xor_sync(0xffffffffu, ps0, 1);
            ps0 += __shfl_xor_sync(0xffffffffu, ps0, 2);
            ps1 += __shfl_xor_sync(0xffffffffu, ps1, 1);
            ps1 += __shfl_xor_sync(0xffffffffu, ps1, 2);
            l0 = l0 * corr0 + ps0;  m0 = mn0;
            l1 = l1 * corr1 + ps1;  m1 = mn1;
            #pragma unroll
            for (int nt = 0; nt < 8; nt++) {
                oacc[nt][0] *= corr0; oacc[nt][1] *= corr0;
                oacc[nt][2] *= corr1; oacc[nt][3] *= corr1;
            }

            // ---- O += P V ----
            #pragma unroll
            for (int kk = 0; kk < 4; kk++) {
                const uint32_t a0 = ph01[2*kk],   a1 = ph23[2*kk];
                const uint32_t a2 = ph01[2*kk+1], a3 = ph23[2*kk+1];
                const uint32_t c0 = pl01[2*kk],   c1 = pl23[2*kk];
                const uint32_t c2 = pl01[2*kk+1], c3 = pl23[2*kk+1];
                #pragma unroll
                for (int dp = 0; dp < 4; dp++) {
                    const int r = kk * 16 + (lane & 15);
                    const int d = dp * 16 + (lane >> 4) * 8;
                    const uint32_t off = r * 128 + (((d >> 3) ^ (r & 7)) << 4);
                    uint32_t b0a, b1a, b0b, b1b;
                    ldsm4t(b0a, b1a, b0b, b1b, uS + 16384 + off);   // Vh
                    mma16816(oacc[2*dp  ], a0, a1, a2, a3, b0a, b1a);
                    mma16816(oacc[2*dp+1], a0, a1, a2, a3, b0b, b1b);
                    mma16816(oacc[2*dp  ], c0, c1, c2, c3, b0a, b1a);
                    mma16816(oacc[2*dp+1], c0, c1, c2, c3, b0b, b1b);
                    ldsm4t(b0a, b1a, b0b, b1b, uS + 24576 + off);   // Vl
                    mma16816(oacc[2*dp  ], a0, a1, a2, a3, b0a, b1a);
                    mma16816(oacc[2*dp+1], a0, a1, a2, a3, b0b, b1b);
                }
            }
        }
        __syncthreads();
    }

    // ---- epilogue: normalize, split, write Y hi/lo planes [B,T,C] ----
    bf16* Yh = (bf16*)g_Yh4;
    bf16* Yl = (bf16*)g_Yl4;
    const float inv0 = 1.0f / l0;
    const float inv1 = 1.0f / l1;
    const int b = bh >> 4, h = bh & 15;
    #pragma unroll
    for (int nt = 0; nt < 8; nt++) {
        const int coln = h * 64 + nt * 8 + tg * 2;
        uint32_t hp, lp;
        split2(oacc[nt][0] * inv0, oacc[nt][1] * inv0, hp, lp);
        *(uint32_t*)&Yh[((size_t)(b*TT + row0))*CC + coln] = hp;
        *(uint32_t*)&Yl[((size_t)(b*TT + row0))*CC + coln] = lp;
        split2(oacc[nt][2] * inv1, oacc[nt][3] * inv1, hp, lp);
        *(uint32_t*)&Yh[((size_t)(b*TT + row0 + 8))*CC + coln] = hp;
        *(uint32_t*)&Yl[((size_t)(b*TT + row0 + 8))*CC + coln] = lp;
    }
}

// ---------------------------------------------------------------------------
extern "C" void kernel_launch(void* const* d_in, const int* in_sizes, int n_in,
                              void* d_out, int out_size)
{
    const float* x      = (const float*)d_in[0];
    const float* b_attn = (const float*)d_in[2];
    const float* b_proj = (const float*)d_in[4];
    float* out = (float*)d_out;

    static bool attr_set = false;
    if (!attr_set) {
        cudaFuncSetAttribute(attn3_kernel,
                             cudaFuncAttributeMaxDynamicSharedMemorySize, ATT_SMEM);
        cudaFuncSetAttribute(hgemm_kernel<0>,
                             cudaFuncAttributeMaxDynamicSharedMemorySize, GEMM_SMEM);
        cudaFuncSetAttribute(hgemm_kernel<1>,
                             cudaFuncAttributeMaxDynamicSharedMemorySize, GEMM_SMEM);
        attr_set = true;
    }

    // 0) one-time fp32 -> bf16 hi/lo split of x and weights
    convert_kernel<<<1024, 256>>>(x, (const float*)d_in[1], (const float*)d_in[3]);
    // 1) QKV GEMM (pipelined) + split-scatter into Q/K/V planes
    hgemm_kernel<0><<<dim3(3*CC/128, MM/128), 256, GEMM_SMEM>>>(b_attn, nullptr, 3*CC);
    // 2) Causal flash attention (pipelined K/V)
    attn3_kernel<<<dim3(TT/128, BB*HH), 256, ATT_SMEM>>>();
    // 3) Output projection (pipelined)
    hgemm_kernel<1><<<dim3(CC/128, MM/128), 256, GEMM_SMEM>>>(b_proj, out, CC);
}

// round 10
// speedup vs baseline: 4.5944x; 1.1069x over previous
#include <cuda_runtime.h>
#include <cuda_bf16.h>
#include <cstdint>

// Problem constants
#define BB 4
#define TT 2048
#define CC 1024
#define HH 16
#define DH 64
#define MM (BB*TT)          // 8192 rows for both GEMMs

// ---------------------------------------------------------------------------
// Pre-split bf16 hi/lo planes (device globals; uint4 for 16B alignment)
// ---------------------------------------------------------------------------
__device__ uint4 g_Xh4[MM*CC/8],  g_Xl4[MM*CC/8];          // x          [M][C]
__device__ uint4 g_Wh4[4*CC*CC/8], g_Wl4[4*CC*CC/8];       // W_attn|W_proj
__device__ uint4 g_Qh4[MM*CC/8],  g_Ql4[MM*CC/8];          // Q [B,H,T,D]
__device__ uint4 g_Kh4[MM*CC/8],  g_Kl4[MM*CC/8];
__device__ uint4 g_Vh4[MM*CC/8],  g_Vl4[MM*CC/8];
__device__ uint4 g_Yh4[MM*CC/8],  g_Yl4[MM*CC/8];          // attn out [B,T,C]

typedef __nv_bfloat16 bf16;

// ---------------------------------------------------------------------------
// primitives
// ---------------------------------------------------------------------------
__device__ __forceinline__ uint32_t smem_u32(const void* p) {
    return (uint32_t)__cvta_generic_to_shared(p);
}
__device__ __forceinline__ void ldsm4(uint32_t& r0, uint32_t& r1, uint32_t& r2, uint32_t& r3, uint32_t a) {
    asm volatile("ldmatrix.sync.aligned.m8n8.x4.shared.b16 {%0,%1,%2,%3},[%4];"
                 : "=r"(r0), "=r"(r1), "=r"(r2), "=r"(r3) : "r"(a));
}
__device__ __forceinline__ void ldsm4t(uint32_t& r0, uint32_t& r1, uint32_t& r2, uint32_t& r3, uint32_t a) {
    asm volatile("ldmatrix.sync.aligned.m8n8.x4.trans.shared.b16 {%0,%1,%2,%3},[%4];"
                 : "=r"(r0), "=r"(r1), "=r"(r2), "=r"(r3) : "r"(a));
}
__device__ __forceinline__ void mma16816(float* c, uint32_t a0, uint32_t a1, uint32_t a2, uint32_t a3,
                                         uint32_t b0, uint32_t b1) {
    asm volatile("mma.sync.aligned.m16n8k16.row.col.f32.bf16.bf16.f32 "
                 "{%0,%1,%2,%3},{%4,%5,%6,%7},{%8,%9},{%0,%1,%2,%3};"
                 : "+f"(c[0]), "+f"(c[1]), "+f"(c[2]), "+f"(c[3])
                 : "r"(a0), "r"(a1), "r"(a2), "r"(a3), "r"(b0), "r"(b1));
}
__device__ __forceinline__ void cp16(uint32_t s, const void* g) {
    asm volatile("cp.async.cg.shared.global [%0], [%1], 16;" :: "r"(s), "l"(g));
}
__device__ __forceinline__ void cp_commit() {
    asm volatile("cp.async.commit_group;" ::: "memory");
}
__device__ __forceinline__ void cp_wait1() {
    asm volatile("cp.async.wait_group 1;" ::: "memory");
}
__device__ __forceinline__ uint32_t pack_bf16(float x, float y) {
    __nv_bfloat162 t = __floats2bfloat162_rn(x, y);
    return *(uint32_t*)&t;
}
__device__ __forceinline__ void splitf(float x, float& h, float& l) {
    h = __bfloat162float(__float2bfloat16(x));
    l = x - h;
}
__device__ __forceinline__ void split2(float x, float y, uint32_t& h, uint32_t& l) {
    float hx, lx, hy, ly;
    splitf(x, hx, lx); splitf(y, hy, ly);
    h = pack_bf16(hx, hy);
    l = pack_bf16(lx, ly);
}

// ---------------------------------------------------------------------------
// One-time split: x, W_attn, W_proj -> bf16 hi/lo planes.
// ---------------------------------------------------------------------------
__global__ void convert_kernel(const float* __restrict__ x,
                               const float* __restrict__ W_attn,
                               const float* __restrict__ W_proj)
{
    bf16* Xh = (bf16*)g_Xh4; bf16* Xl = (bf16*)g_Xl4;
    bf16* Wh = (bf16*)g_Wh4; bf16* Wl = (bf16*)g_Wl4;
    const int stride = gridDim.x * blockDim.x;
    const int t0 = blockIdx.x * blockDim.x + threadIdx.x;

    for (int i = t0; i < MM*CC/4; i += stride) {
        float4 v = *(const float4*)&x[(size_t)i*4];
        uint32_t h01, l01, h23, l23;
        split2(v.x, v.y, h01, l01);
        split2(v.z, v.w, h23, l23);
        *(uint2*)&Xh[(size_t)i*4] = make_uint2(h01, h23);
        *(uint2*)&Xl[(size_t)i*4] = make_uint2(l01, l23);
    }
    for (int i = t0; i < 3*CC*CC/4; i += stride) {
        float4 v = *(const float4*)&W_attn[(size_t)i*4];
        uint32_t h01, l01, h23, l23;
        split2(v.x, v.y, h01, l01);
        split2(v.z, v.w, h23, l23);
        *(uint2*)&Wh[(size_t)i*4] = make_uint2(h01, h23);
        *(uint2*)&Wl[(size_t)i*4] = make_uint2(l01, l23);
    }
    for (int i = t0; i < CC*CC/4; i += stride) {
        float4 v = *(const float4*)&W_proj[(size_t)i*4];
        uint32_t h01, l01, h23, l23;
        split2(v.x, v.y, h01, l01);
        split2(v.z, v.w, h23, l23);
        *(uint2*)&Wh[(size_t)(3*CC*CC) + (size_t)i*4] = make_uint2(h01, h23);
        *(uint2*)&Wl[(size_t)(3*CC*CC) + (size_t)i*4] = make_uint2(l01, l23);
    }
}

// ---------------------------------------------------------------------------
// Tensor-core GEMM, pre-split operands, cp.async 3-stage pipeline.
// Block 128x128x64, 256 threads, 8 warps (4m x 2n), warp tile 32x64.
// Smem: 3 stages x 64KB. One __syncthreads per k-tile; wait_group 1.
// ---------------------------------------------------------------------------
#define GEMM_STAGE 65536
#define GEMM_SMEM  (3*GEMM_STAGE)

template<int MODE>
__device__ __forceinline__ void gemm_load_tile(uint32_t uS, const bf16* Ah, const bf16* Al,
                                               const bf16* Wh, const bf16* Wl,
                                               int bm, int bn, int k0, int N, int tid)
{
    #pragma unroll
    for (int i = 0; i < 4; i++) {
        const int c  = i * 256 + tid;
        const int m  = c >> 3;
        const int k8 = c & 7;
        const size_t g = (size_t)(bm + m) * CC + k0 + k8 * 8;
        const uint32_t off = m * 128 + ((k8 ^ (m & 7)) << 4);
        cp16(uS + off,         &Ah[g]);
        cp16(uS + 16384 + off, &Al[g]);
    }
    #pragma unroll
    for (int i = 0; i < 4; i++) {
        const int c  = i * 256 + tid;
        const int k  = c >> 4;
        const int n8 = c & 15;
        const size_t g = (size_t)(k0 + k) * N + bn + n8 * 8;
        const uint32_t off = k * 256 + ((n8 ^ (k & 7)) << 4);
        cp16(uS + 32768 + off, &Wh[g]);
        cp16(uS + 49152 + off, &Wl[g]);
    }
}

template<int MODE>
__global__ __launch_bounds__(256) void hgemm_kernel(const float* __restrict__ bias,
                                                    float* __restrict__ out,
                                                    int N)
{
    extern __shared__ char smg[];
    const uint32_t uBase = smem_u32(smg);

    const bf16* Ah = (MODE == 0) ? (const bf16*)g_Xh4 : (const bf16*)g_Yh4;
    const bf16* Al = (MODE == 0) ? (const bf16*)g_Xl4 : (const bf16*)g_Yl4;
    const bf16* Wh = (const bf16*)g_Wh4 + (MODE == 0 ? 0 : (size_t)3*CC*CC);
    const bf16* Wl = (const bf16*)g_Wl4 + (MODE == 0 ? 0 : (size_t)3*CC*CC);

    const int bm = blockIdx.y * 128;
    const int bn = blockIdx.x * 128;
    const int tid  = threadIdx.x;
    const int wid  = tid >> 5;
    const int lane = tid & 31;
    const int warp_m = wid & 3;
    const int warp_n = wid >> 2;

    float acc[2][8][4];
    #pragma unroll
    for (int mt = 0; mt < 2; mt++)
        #pragma unroll
        for (int nt = 0; nt < 8; nt++)
            #pragma unroll
            for (int r = 0; r < 4; r++) acc[mt][nt][r] = 0.f;

    // prologue: stages 0,1
    gemm_load_tile<MODE>(uBase, Ah, Al, Wh, Wl, bm, bn, 0, N, tid);
    cp_commit();
    gemm_load_tile<MODE>(uBase + GEMM_STAGE, Ah, Al, Wh, Wl, bm, bn, 64, N, tid);
    cp_commit();

    const int NT = CC / 64;    // 16
    int stage = 0;
    for (int kt = 0; kt < NT; kt++) {
        cp_wait1();              // tile kt (issued 2 iterations back) complete
        __syncthreads();
        if (kt + 2 < NT) {
            int s2 = stage + 2; if (s2 >= 3) s2 -= 3;
            gemm_load_tile<MODE>(uBase + s2 * GEMM_STAGE,
                                 Ah, Al, Wh, Wl, bm, bn, (kt + 2) * 64, N, tid);
        }
        cp_commit();             // always (possibly empty) — keeps group count
        const uint32_t uAh = uBase + stage * GEMM_STAGE;
        const uint32_t uAl = uAh + 16384;
        const uint32_t uBh = uAh + 32768;
        const uint32_t uBl = uAh + 49152;

        #pragma unroll
        for (int ks = 0; ks < 64; ks += 16) {
            uint32_t ah[2][4], al[2][4];
            #pragma unroll
            for (int mt = 0; mt < 2; mt++) {
                const int m = warp_m * 32 + mt * 16 + (lane & 15);
                const int k = ks + (lane >> 4) * 8;
                const uint32_t off = m * 128 + (((k >> 3) ^ (m & 7)) << 4);
                ldsm4(ah[mt][0], ah[mt][1], ah[mt][2], ah[mt][3], uAh + off);
                ldsm4(al[mt][0], al[mt][1], al[mt][2], al[mt][3], uAl + off);
            }
            uint32_t bh[8][2], bl[8][2];
            #pragma unroll
            for (int p = 0; p < 4; p++) {
                const int k = ks + ((lane >> 3) & 1) * 8 + (lane & 7);
                const int n = warp_n * 64 + p * 16 + (lane >> 4) * 8;
                const uint32_t off = k * 256 + (((n >> 3) ^ (k & 7)) << 4);
                ldsm4t(bh[2*p][0], bh[2*p][1], bh[2*p+1][0], bh[2*p+1][1], uBh + off);
                ldsm4t(bl[2*p][0], bl[2*p][1], bl[2*p+1][0], bl[2*p+1][1], uBl + off);
            }
            #pragma unroll
            for (int mt = 0; mt < 2; mt++)
                #pragma unroll
                for (int nt = 0; nt < 8; nt++) {
                    mma16816(acc[mt][nt], ah[mt][0], ah[mt][1], ah[mt][2], ah[mt][3],
                             bh[nt][0], bh[nt][1]);
                    mma16816(acc[mt][nt], ah[mt][0], ah[mt][1], ah[mt][2], ah[mt][3],
                             bl[nt][0], bl[nt][1]);
                    mma16816(acc[mt][nt], al[mt][0], al[mt][1], al[mt][2], al[mt][3],
                             bh[nt][0], bh[nt][1]);
                }
        }
        stage++; if (stage == 3) stage = 0;
    }

    // ---- epilogue ----
    bf16* Qh = (bf16*)g_Qh4; bf16* Ql = (bf16*)g_Ql4;
    bf16* Kh = (bf16*)g_Kh4; bf16* Kl = (bf16*)g_Kl4;
    bf16* Vh = (bf16*)g_Vh4; bf16* Vl = (bf16*)g_Vl4;
    const int g  = lane >> 2;
    const int tg = lane & 3;
    #pragma unroll
    for (int mt = 0; mt < 2; mt++)
        #pragma unroll
        for (int nt = 0; nt < 8; nt++) {
            const int gn = bn + warp_n * 64 + nt * 8 + tg * 2;
            #pragma unroll
            for (int half = 0; half < 2; half++) {
                const int gm = bm + warp_m * 32 + mt * 16 + g + half * 8;
                const float v0 = acc[mt][nt][half * 2 + 0] + bias[gn];
                const float v1 = acc[mt][nt][half * 2 + 1] + bias[gn + 1];
                if (MODE == 0) {
                    uint32_t hp, lp;
                    split2(v0, v1, hp, lp);
                    const int which = gn >> 10;
                    const int c = gn & 1023;
                    const int h = c >> 6, d = c & 63;
                    const int b = gm >> 11;
                    const int t = gm & 2047;
                    const size_t idx = ((size_t)((b*HH + h)*TT + t))*DH + d;
                    if (which == 0)      { *(uint32_t*)&Qh[idx] = hp; *(uint32_t*)&Ql[idx] = lp; }
                    else if (which == 1) { *(uint32_t*)&Kh[idx] = hp; *(uint32_t*)&Kl[idx] = lp; }
                    else                 { *(uint32_t*)&Vh[idx] = hp; *(uint32_t*)&Vl[idx] = lp; }
                } else {
                    out[(size_t)gm * N + gn    ] = v0;
                    out[(size_t)gm * N + gn + 1] = v1;
                }
            }
        }
}

// ---------------------------------------------------------------------------
// Flash attention (tensor-core, FA2 layout), pre-split planes,
// cp.async 3-stage pipelined K/V tiles (3 x 32KB). Longest-first schedule.
// ---------------------------------------------------------------------------
#define ATT_STAGE 32768
#define ATT_SMEM  (3*ATT_STAGE)

__device__ __forceinline__ void attn_load_tile(uint32_t uS,
                                               const bf16* Kh, const bf16* Kl,
                                               const bf16* Vh, const bf16* Vl,
                                               int kt, int tid)
{
    #pragma unroll
    for (int i = 0; i < 2; i++) {
        const int c  = i * 256 + tid;
        const int r  = c >> 3;
        const int d8 = c & 7;
        const size_t gg = (size_t)(kt*64 + r) * DH + d8 * 8;
        const uint32_t off = r * 128 + ((d8 ^ (r & 7)) << 4);
        cp16(uS + off,         &Kh[gg]);
        cp16(uS + 8192 + off,  &Kl[gg]);
        cp16(uS + 16384 + off, &Vh[gg]);
        cp16(uS + 24576 + off, &Vl[gg]);
    }
}

__global__ __launch_bounds__(256) void attn3_kernel()
{
    extern __shared__ char smx[];
    const uint32_t uB = smem_u32(smx);

    // longest-first: big q-tiles scheduled first
    const int qtb = (TT/128 - 1) - (blockIdx.x >> 6);
    const int bh  = blockIdx.x & 63;
    const int qb  = qtb * 128;
    const int tid = threadIdx.x;
    const int wid = tid >> 5;
    const int lane = tid & 31;

    const bf16* Qh = (const bf16*)g_Qh4 + (size_t)bh * TT * DH;
    const bf16* Ql = (const bf16*)g_Ql4 + (size_t)bh * TT * DH;
    const bf16* Kh = (const bf16*)g_Kh4 + (size_t)bh * TT * DH;
    const bf16* Kl = (const bf16*)g_Kl4 + (size_t)bh * TT * DH;
    const bf16* Vh = (const bf16*)g_Vh4 + (size_t)bh * TT * DH;
    const bf16* Vl = (const bf16*)g_Vl4 + (size_t)bh * TT * DH;

    // ---- stage Q tile (pure copy, swizzled; uses stage-0 region) ----
    #pragma unroll
    for (int i = 0; i < 4; i++) {
        const int c  = i * 256 + tid;
        const int m  = c >> 3;
        const int d8 = c & 7;
        const size_t g = (size_t)(qb + m) * DH + d8 * 8;
        const uint32_t off = m * 128 + ((d8 ^ (m & 7)) << 4);
        *(uint4*)(smx + off)         = *(const uint4*)&Qh[g];
        *(uint4*)(smx + 16384 + off) = *(const uint4*)&Ql[g];
    }
    __syncthreads();

    uint32_t qh[4][4], ql[4][4];
    {
        const int m = wid * 16 + (lane & 15);
        #pragma unroll
        for (int ks = 0; ks < 4; ks++) {
            const int k = ks * 16 + (lane >> 4) * 8;
            const uint32_t off = m * 128 + (((k >> 3) ^ (m & 7)) << 4);
            ldsm4(qh[ks][0], qh[ks][1], qh[ks][2], qh[ks][3], uB + off);
            ldsm4(ql[ks][0], ql[ks][1], ql[ks][2], ql[ks][3], uB + 16384 + off);
        }
    }
    __syncthreads();   // Q smem region free; stage 0 reuses it

    float oacc[8][4];
    #pragma unroll
    for (int nt = 0; nt < 8; nt++)
        #pragma unroll
        for (int r = 0; r < 4; r++) oacc[nt][r] = 0.f;
    float m0 = -1e30f, m1 = -1e30f, l0 = 0.f, l1 = 0.f;

    const int qw = qb + wid * 16;
    const int g  = lane >> 2;
    const int tg = lane & 3;
    const int row0 = qw + g;
    const float scale = 0.125f;
    const int ktmax = 2 * qtb + 1;

    // prologue: stages 0,1 (ktmax >= 1 always)
    attn_load_tile(uB, Kh, Kl, Vh, Vl, 0, tid);
    cp_commit();
    attn_load_tile(uB + ATT_STAGE, Kh, Kl, Vh, Vl, 1, tid);
    cp_commit();

    int stage = 0;
    for (int kt = 0; kt <= ktmax; kt++) {
        cp_wait1();
        __syncthreads();
        if (kt + 2 <= ktmax) {
            int s2 = stage + 2; if (s2 >= 3) s2 -= 3;
            attn_load_tile(uB + s2 * ATT_STAGE, Kh, Kl, Vh, Vl, kt + 2, tid);
        }
        cp_commit();
        const uint32_t uS = uB + stage * ATT_STAGE;

        if (kt * 64 <= qw + 15) {
            // ---- S = Q K^T ----
            float sacc[8][4];
            #pragma unroll
            for (int nt = 0; nt < 8; nt++)
                #pragma unroll
                for (int r = 0; r < 4; r++) sacc[nt][r] = 0.f;

            #pragma unroll
            for (int ks = 0; ks < 4; ks++) {
                #pragma unroll
                for (int p = 0; p < 4; p++) {
                    const int n = p * 16 + (lane & 15);
                    const int k = ks * 16 + (lane >> 4) * 8;
                    const uint32_t off = n * 128 + (((k >> 3) ^ (n & 7)) << 4);
                    uint32_t b0a, b0b, b1a, b1b;
                    ldsm4(b0a, b0b, b1a, b1b, uS + off);          // Kh
                    mma16816(sacc[2*p  ], qh[ks][0], qh[ks][1], qh[ks][2], qh[ks][3], b0a, b1a);
                    mma16816(sacc[2*p+1], qh[ks][0], qh[ks][1], qh[ks][2], qh[ks][3], b0b, b1b);
                    mma16816(sacc[2*p  ], ql[ks][0], ql[ks][1], ql[ks][2], ql[ks][3], b0a, b1a);
                    mma16816(sacc[2*p+1], ql[ks][0], ql[ks][1], ql[ks][2], ql[ks][3], b0b, b1b);
                    ldsm4(b0a, b0b, b1a, b1b, uS + 8192 + off);   // Kl
                    mma16816(sacc[2*p  ], qh[ks][0], qh[ks][1], qh[ks][2], qh[ks][3], b0a, b1a);
                    mma16816(sacc[2*p+1], qh[ks][0], qh[ks][1], qh[ks][2], qh[ks][3], b0b, b1b);
                }
            }

            // ---- scale + causal mask ----
            if (kt * 64 + 63 > qw) {
                #pragma unroll
                for (int nt = 0; nt < 8; nt++) {
                    const int col = kt * 64 + nt * 8 + tg * 2;
                    sacc[nt][0] = (col     <= row0    ) ? sacc[nt][0] * scale : -1e30f;
                    sacc[nt][1] = (col + 1 <= row0    ) ? sacc[nt][1] * scale : -1e30f;
                    sacc[nt][2] = (col     <= row0 + 8) ? sacc[nt][2] * scale : -1e30f;
                    sacc[nt][3] = (col + 1 <= row0 + 8) ? sacc[nt][3] * scale : -1e30f;
                }
            } else {
                #pragma unroll
                for (int nt = 0; nt < 8; nt++)
                    #pragma unroll
                    for (int r = 0; r < 4; r++) sacc[nt][r] *= scale;
            }

            // ---- online softmax ----
            float mx0 = -1e30f, mx1 = -1e30f;
            #pragma unroll
            for (int nt = 0; nt < 8; nt++) {
                mx0 = fmaxf(mx0, fmaxf(sacc[nt][0], sacc[nt][1]));
                mx1 = fmaxf(mx1, fmaxf(sacc[nt][2], sacc[nt][3]));
            }
            mx0 = fmaxf(mx0, __shfl_xor_sync(0xffffffffu, mx0, 1));
            mx0 = fmaxf(mx0, __shfl_xor_sync(0xffffffffu, mx0, 2));
            mx1 = fmaxf(mx1, __shfl_xor_sync(0xffffffffu, mx1, 1));
            mx1 = fmaxf(mx1, __shfl_xor_sync(0xffffffffu, mx1, 2));
            const float mn0 = fmaxf(m0, mx0);
            const float mn1 = fmaxf(m1, mx1);
            const float corr0 = __expf(m0 - mn0);
            const float corr1 = __expf(m1 - mn1);

            uint32_t ph01[8], ph23[8], pl01[8], pl23[8];
            float ps0 = 0.f, ps1 = 0.f;
            #pragma unroll
            for (int nt = 0; nt < 8; nt++) {
                const float p0 = __expf(sacc[nt][0] - mn0);
                const float p1 = __expf(sacc[nt][1] - mn0);
                const float p2 = __expf(sacc[nt][2] - mn1);
                const float p3 = __expf(sacc[nt][3] - mn1);
                ps0 += p0 + p1;
                ps1 += p2 + p3;
                split2(p0, p1, ph01[nt], pl01[nt]);
                split2(p2, p3, ph23[nt], pl23[nt]);
            }
            ps0 += __shfl_xor_sync(0xffffffffu, ps0, 1);
            ps0 += __shfl_xor_sync(0xffffffffu, ps0, 2);
            ps1 += __shfl_xor_sync(0xffffffffu, ps1, 1);
            ps1 += __shfl_xor_sync(0xffffffffu, ps1, 2);
            l0 = l0 * corr0 + ps0;  m0 = mn0;
            l1 = l1 * corr1 + ps1;  m1 = mn1;
            #pragma unroll
            for (int nt = 0; nt < 8; nt++) {
                oacc[nt][0] *= corr0; oacc[nt][1] *= corr0;
                oacc[nt][2] *= corr1; oacc[nt][3] *= corr1;
            }

            // ---- O += P V ----
            #pragma unroll
            for (int kk = 0; kk < 4; kk++) {
                const uint32_t a0 = ph01[2*kk],   a1 = ph23[2*kk];
                const uint32_t a2 = ph01[2*kk+1], a3 = ph23[2*kk+1];
                const uint32_t c0 = pl01[2*kk],   c1 = pl23[2*kk];
                const uint32_t c2 = pl01[2*kk+1], c3 = pl23[2*kk+1];
                #pragma unroll
                for (int dp = 0; dp < 4; dp++) {
                    const int r = kk * 16 + (lane & 15);
                    const int d = dp * 16 + (lane >> 4) * 8;
                    const uint32_t off = r * 128 + (((d >> 3) ^ (r & 7)) << 4);
                    uint32_t b0a, b1a, b0b, b1b;
                    ldsm4t(b0a, b1a, b0b, b1b, uS + 16384 + off);   // Vh
                    mma16816(oacc[2*dp  ], a0, a1, a2, a3, b0a, b1a);
                    mma16816(oacc[2*dp+1], a0, a1, a2, a3, b0b, b1b);
                    mma16816(oacc[2*dp  ], c0, c1, c2, c3, b0a, b1a);
                    mma16816(oacc[2*dp+1], c0, c1, c2, c3, b0b, b1b);
                    ldsm4t(b0a, b1a, b0b, b1b, uS + 24576 + off);   // Vl
                    mma16816(oacc[2*dp  ], a0, a1, a2, a3, b0a, b1a);
                    mma16816(oacc[2*dp+1], a0, a1, a2, a3, b0b, b1b);
                }
            }
        }
        stage++; if (stage == 3) stage = 0;
    }

    // ---- epilogue: normalize, split, write Y hi/lo planes [B,T,C] ----
    bf16* Yh = (bf16*)g_Yh4;
    bf16* Yl = (bf16*)g_Yl4;
    const float inv0 = 1.0f / l0;
    const float inv1 = 1.0f / l1;
    const int b = bh >> 4, h = bh & 15;
    #pragma unroll
    for (int nt = 0; nt < 8; nt++) {
        const int coln = h * 64 + nt * 8 + tg * 2;
        uint32_t hp, lp;
        split2(oacc[nt][0] * inv0, oacc[nt][1] * inv0, hp, lp);
        *(uint32_t*)&Yh[((size_t)(b*TT + row0))*CC + coln] = hp;
        *(uint32_t*)&Yl[((size_t)(b*TT + row0))*CC + coln] = lp;
        split2(oacc[nt][2] * inv1, oacc[nt][3] * inv1, hp, lp);
        *(uint32_t*)&Yh[((size_t)(b*TT + row0 + 8))*CC + coln] = hp;
        *(uint32_t*)&Yl[((size_t)(b*TT + row0 + 8))*CC + coln] = lp;
    }
}

// ---------------------------------------------------------------------------
extern "C" void kernel_launch(void* const* d_in, const int* in_sizes, int n_in,
                              void* d_out, int out_size)
{
    const float* x      = (const float*)d_in[0];
    const float* b_attn = (const float*)d_in[2];
    const float* b_proj = (const float*)d_in[4];
    float* out = (float*)d_out;

    static bool attr_set = false;
    if (!attr_set) {
        cudaFuncSetAttribute(attn3_kernel,
                             cudaFuncAttributeMaxDynamicSharedMemorySize, ATT_SMEM);
        cudaFuncSetAttribute(hgemm_kernel<0>,
                             cudaFuncAttributeMaxDynamicSharedMemorySize, GEMM_SMEM);
        cudaFuncSetAttribute(hgemm_kernel<1>,
                             cudaFuncAttributeMaxDynamicSharedMemorySize, GEMM_SMEM);
        attr_set = true;
    }

    // 0) one-time fp32 -> bf16 hi/lo split of x and weights
    convert_kernel<<<1024, 256>>>(x, (const float*)d_in[1], (const float*)d_in[3]);
    // 1) QKV GEMM (3-stage pipeline) + split-scatter into Q/K/V planes
    hgemm_kernel<0><<<dim3(3*CC/128, MM/128), 256, GEMM_SMEM>>>(b_attn, nullptr, 3*CC);
    // 2) Causal flash attention (3-stage pipeline, longest-first)
    attn3_kernel<<<TT/128 * BB*HH, 256, ATT_SMEM>>>();
    // 3) Output projection (3-stage pipeline)
    hgemm_kernel<1><<<dim3(CC/128, MM/128), 256, GEMM_SMEM>>>(b_proj, out, CC);
}

// round 12
// speedup vs baseline: 4.6770x; 1.0180x over previous
#include <cuda_runtime.h>
#include <cuda_bf16.h>
#include <cstdint>

// Problem constants
#define BB 4
#define TT 2048
#define CC 1024
#define HH 16
#define DH 64
#define MM (BB*TT)          // 8192 rows for both GEMMs

// ---------------------------------------------------------------------------
// Pre-split bf16 hi/lo planes (device globals; uint4 for 16B alignment)
// ---------------------------------------------------------------------------
__device__ uint4 g_Xh4[MM*CC/8],  g_Xl4[MM*CC/8];          // x          [M][C]
__device__ uint4 g_Wh4[4*CC*CC/8], g_Wl4[4*CC*CC/8];       // W_attn|W_proj
__device__ uint4 g_Qh4[MM*CC/8],  g_Ql4[MM*CC/8];          // Q [B,H,T,D]
__device__ uint4 g_Kh4[MM*CC/8],  g_Kl4[MM*CC/8];
__device__ uint4 g_Vh4[MM*CC/8],  g_Vl4[MM*CC/8];
__device__ uint4 g_Yh4[MM*CC/8],  g_Yl4[MM*CC/8];          // attn out [B,T,C]

typedef __nv_bfloat16 bf16;

// ---------------------------------------------------------------------------
// primitives
// ---------------------------------------------------------------------------
__device__ __forceinline__ uint32_t smem_u32(const void* p) {
    return (uint32_t)__cvta_generic_to_shared(p);
}
__device__ __forceinline__ void ldsm4(uint32_t& r0, uint32_t& r1, uint32_t& r2, uint32_t& r3, uint32_t a) {
    asm volatile("ldmatrix.sync.aligned.m8n8.x4.shared.b16 {%0,%1,%2,%3},[%4];"
                 : "=r"(r0), "=r"(r1), "=r"(r2), "=r"(r3) : "r"(a));
}
__device__ __forceinline__ void ldsm4t(uint32_t& r0, uint32_t& r1, uint32_t& r2, uint32_t& r3, uint32_t a) {
    asm volatile("ldmatrix.sync.aligned.m8n8.x4.trans.shared.b16 {%0,%1,%2,%3},[%4];"
                 : "=r"(r0), "=r"(r1), "=r"(r2), "=r"(r3) : "r"(a));
}
__device__ __forceinline__ void mma16816(float* c, uint32_t a0, uint32_t a1, uint32_t a2, uint32_t a3,
                                         uint32_t b0, uint32_t b1) {
    asm volatile("mma.sync.aligned.m16n8k16.row.col.f32.bf16.bf16.f32 "
                 "{%0,%1,%2,%3},{%4,%5,%6,%7},{%8,%9},{%0,%1,%2,%3};"
                 : "+f"(c[0]), "+f"(c[1]), "+f"(c[2]), "+f"(c[3])
                 : "r"(a0), "r"(a1), "r"(a2), "r"(a3), "r"(b0), "r"(b1));
}
__device__ __forceinline__ void cp16(uint32_t s, const void* g) {
    asm volatile("cp.async.cg.shared.global [%0], [%1], 16;" :: "r"(s), "l"(g));
}
__device__ __forceinline__ void cp_commit() {
    asm volatile("cp.async.commit_group;" ::: "memory");
}
__device__ __forceinline__ void cp_wait1() {
    asm volatile("cp.async.wait_group 1;" ::: "memory");
}
__device__ __forceinline__ uint32_t pack_bf16(float x, float y) {
    __nv_bfloat162 t = __floats2bfloat162_rn(x, y);
    return *(uint32_t*)&t;
}
__device__ __forceinline__ void splitf(float x, float& h, float& l) {
    h = __bfloat162float(__float2bfloat16(x));
    l = x - h;
}
__device__ __forceinline__ void split2(float x, float y, uint32_t& h, uint32_t& l) {
    float hx, lx, hy, ly;
    splitf(x, hx, lx); splitf(y, hy, ly);
    h = pack_bf16(hx, hy);
    l = pack_bf16(lx, ly);
}

// ---------------------------------------------------------------------------
// One-time split: x, W_attn, W_proj -> bf16 hi/lo planes.
// ---------------------------------------------------------------------------
__global__ void convert_kernel(const float* __restrict__ x,
                               const float* __restrict__ W_attn,
                               const float* __restrict__ W_proj)
{
    bf16* Xh = (bf16*)g_Xh4; bf16* Xl = (bf16*)g_Xl4;
    bf16* Wh = (bf16*)g_Wh4; bf16* Wl = (bf16*)g_Wl4;
    const int stride = gridDim.x * blockDim.x;
    const int t0 = blockIdx.x * blockDim.x + threadIdx.x;

    for (int i = t0; i < MM*CC/4; i += stride) {
        float4 v = *(const float4*)&x[(size_t)i*4];
        uint32_t h01, l01, h23, l23;
        split2(v.x, v.y, h01, l01);
        split2(v.z, v.w, h23, l23);
        *(uint2*)&Xh[(size_t)i*4] = make_uint2(h01, h23);
        *(uint2*)&Xl[(size_t)i*4] = make_uint2(l01, l23);
    }
    for (int i = t0; i < 3*CC*CC/4; i += stride) {
        float4 v = *(const float4*)&W_attn[(size_t)i*4];
        uint32_t h01, l01, h23, l23;
        split2(v.x, v.y, h01, l01);
        split2(v.z, v.w, h23, l23);
        *(uint2*)&Wh[(size_t)i*4] = make_uint2(h01, h23);
        *(uint2*)&Wl[(size_t)i*4] = make_uint2(l01, l23);
    }
    for (int i = t0; i < CC*CC/4; i += stride) {
        float4 v = *(const float4*)&W_proj[(size_t)i*4];
        uint32_t h01, l01, h23, l23;
        split2(v.x, v.y, h01, l01);
        split2(v.z, v.w, h23, l23);
        *(uint2*)&Wh[(size_t)(3*CC*CC) + (size_t)i*4] = make_uint2(h01, h23);
        *(uint2*)&Wl[(size_t)(3*CC*CC) + (size_t)i*4] = make_uint2(l01, l23);
    }
}

// ---------------------------------------------------------------------------
// Tensor-core GEMM, pre-split operands, cp.async 3-stage pipeline.
// Block 128x128x64, 512 threads, 16 warps (4m x 4n), warp tile 32x32.
// Smem: 3 stages x 64KB. One __syncthreads per k-tile; wait_group 1.
// ---------------------------------------------------------------------------
#define GEMM_STAGE 65536
#define GEMM_SMEM  (3*GEMM_STAGE)

template<int MODE>
__device__ __forceinline__ void gemm_load_tile(uint32_t uS, const bf16* Ah, const bf16* Al,
                                               const bf16* Wh, const bf16* Wl,
                                               int bm, int bn, int k0, int N, int tid)
{
    #pragma unroll
    for (int i = 0; i < 2; i++) {
        const int c  = i * 512 + tid;
        const int m  = c >> 3;
        const int k8 = c & 7;
        const size_t g = (size_t)(bm + m) * CC + k0 + k8 * 8;
        const uint32_t off = m * 128 + ((k8 ^ (m & 7)) << 4);
        cp16(uS + off,         &Ah[g]);
        cp16(uS + 16384 + off, &Al[g]);
    }
    #pragma unroll
    for (int i = 0; i < 2; i++) {
        const int c  = i * 512 + tid;
        const int k  = c >> 4;
        const int n8 = c & 15;
        const size_t g = (size_t)(k0 + k) * N + bn + n8 * 8;
        const uint32_t off = k * 256 + ((n8 ^ (k & 7)) << 4);
        cp16(uS + 32768 + off, &Wh[g]);
        cp16(uS + 49152 + off, &Wl[g]);
    }
}

template<int MODE>
__global__ __launch_bounds__(512) void hgemm_kernel(const float* __restrict__ bias,
                                                    float* __restrict__ out,
                                                    int N)
{
    extern __shared__ char smg[];
    const uint32_t uBase = smem_u32(smg);

    const bf16* Ah = (MODE == 0) ? (const bf16*)g_Xh4 : (const bf16*)g_Yh4;
    const bf16* Al = (MODE == 0) ? (const bf16*)g_Xl4 : (const bf16*)g_Yl4;
    const bf16* Wh = (const bf16*)g_Wh4 + (MODE == 0 ? 0 : (size_t)3*CC*CC);
    const bf16* Wl = (const bf16*)g_Wl4 + (MODE == 0 ? 0 : (size_t)3*CC*CC);

    const int bm = blockIdx.y * 128;
    const int bn = blockIdx.x * 128;
    const int tid  = threadIdx.x;
    const int wid  = tid >> 5;
    const int lane = tid & 31;
    const int warp_m = wid & 3;       // 0..3 -> m offset *32
    const int warp_n = wid >> 2;      // 0..3 -> n offset *32

    float acc[2][4][4];
    #pragma unroll
    for (int mt = 0; mt < 2; mt++)
        #pragma unroll
        for (int nt = 0; nt < 4; nt++)
            #pragma unroll
            for (int r = 0; r < 4; r++) acc[mt][nt][r] = 0.f;

    // prologue: stages 0,1
    gemm_load_tile<MODE>(uBase, Ah, Al, Wh, Wl, bm, bn, 0, N, tid);
    cp_commit();
    gemm_load_tile<MODE>(uBase + GEMM_STAGE, Ah, Al, Wh, Wl, bm, bn, 64, N, tid);
    cp_commit();

    const int NT = CC / 64;    // 16
    int stage = 0;
    for (int kt = 0; kt < NT; kt++) {
        cp_wait1();              // tile kt (issued 2 iterations back) complete
        __syncthreads();
        if (kt + 2 < NT) {
            int s2 = stage + 2; if (s2 >= 3) s2 -= 3;
            gemm_load_tile<MODE>(uBase + s2 * GEMM_STAGE,
                                 Ah, Al, Wh, Wl, bm, bn, (kt + 2) * 64, N, tid);
        }
        cp_commit();             // always (possibly empty) — keeps group count
        const uint32_t uAh = uBase + stage * GEMM_STAGE;
        const uint32_t uAl = uAh + 16384;
        const uint32_t uBh = uAh + 32768;
        const uint32_t uBl = uAh + 49152;

        #pragma unroll
        for (int ks = 0; ks < 64; ks += 16) {
            uint32_t ah[2][4], al[2][4];
            #pragma unroll
            for (int mt = 0; mt < 2; mt++) {
                const int m = warp_m * 32 + mt * 16 + (lane & 15);
                const int k = ks + (lane >> 4) * 8;
                const uint32_t off = m * 128 + (((k >> 3) ^ (m & 7)) << 4);
                ldsm4(ah[mt][0], ah[mt][1], ah[mt][2], ah[mt][3], uAh + off);
                ldsm4(al[mt][0], al[mt][1], al[mt][2], al[mt][3], uAl + off);
            }
            uint32_t bh[4][2], bl[4][2];
            #pragma unroll
            for (int p = 0; p < 2; p++) {
                const int k = ks + ((lane >> 3) & 1) * 8 + (lane & 7);
                const int n = warp_n * 32 + p * 16 + (lane >> 4) * 8;
                const uint32_t off = k * 256 + (((n >> 3) ^ (k & 7)) << 4);
                ldsm4t(bh[2*p][0], bh[2*p][1], bh[2*p+1][0], bh[2*p+1][1], uBh + off);
                ldsm4t(bl[2*p][0], bl[2*p][1], bl[2*p+1][0], bl[2*p+1][1], uBl + off);
            }
            #pragma unroll
            for (int mt = 0; mt < 2; mt++)
                #pragma unroll
                for (int nt = 0; nt < 4; nt++) {
                    mma16816(acc[mt][nt], ah[mt][0], ah[mt][1], ah[mt][2], ah[mt][3],
                             bh[nt][0], bh[nt][1]);
                    mma16816(acc[mt][nt], ah[mt][0], ah[mt][1], ah[mt][2], ah[mt][3],
                             bl[nt][0], bl[nt][1]);
                    mma16816(acc[mt][nt], al[mt][0], al[mt][1], al[mt][2], al[mt][3],
                             bh[nt][0], bh[nt][1]);
                }
        }
        stage++; if (stage == 3) stage = 0;
    }

    // ---- epilogue ----
    bf16* Qh = (bf16*)g_Qh4; bf16* Ql = (bf16*)g_Ql4;
    bf16* Kh = (bf16*)g_Kh4; bf16* Kl = (bf16*)g_Kl4;
    bf16* Vh = (bf16*)g_Vh4; bf16* Vl = (bf16*)g_Vl4;
    const int g  = lane >> 2;
    const int tg = lane & 3;
    #pragma unroll
    for (int mt = 0; mt < 2; mt++)
        #pragma unroll
        for (int nt = 0; nt < 4; nt++) {
            const int gn = bn + warp_n * 32 + nt * 8 + tg * 2;
            #pragma unroll
            for (int half = 0; half < 2; half++) {
                const int gm = bm + warp_m * 32 + mt * 16 + g + half * 8;
                const float v0 = acc[mt][nt][half * 2 + 0] + bias[gn];
                const float v1 = acc[mt][nt][half * 2 + 1] + bias[gn + 1];
                if (MODE == 0) {
                    uint32_t hp, lp;
                    split2(v0, v1, hp, lp);
                    const int which = gn >> 10;
                    const int c = gn & 1023;
                    const int h = c >> 6, d = c & 63;
                    const int b = gm >> 11;
                    const int t = gm & 2047;
                    const size_t idx = ((size_t)((b*HH + h)*TT + t))*DH + d;
                    if (which == 0)      { *(uint32_t*)&Qh[idx] = hp; *(uint32_t*)&Ql[idx] = lp; }
                    else if (which == 1) { *(uint32_t*)&Kh[idx] = hp; *(uint32_t*)&Kl[idx] = lp; }
                    else                 { *(uint32_t*)&Vh[idx] = hp; *(uint32_t*)&Vl[idx] = lp; }
                } else {
                    out[(size_t)gm * N + gn    ] = v0;
                    out[(size_t)gm * N + gn + 1] = v1;
                }
            }
        }
}

// ---------------------------------------------------------------------------
// Flash attention (tensor-core, FA2 layout), pre-split planes,
// cp.async 3-stage pipelined K/V tiles (3 x 32KB). Longest-first schedule.
// Softmax in base-2 domain (log2e folded into scale).
// ---------------------------------------------------------------------------
#define ATT_STAGE 32768
#define ATT_SMEM  (3*ATT_STAGE)

__device__ __forceinline__ void attn_load_tile(uint32_t uS,
                                               const bf16* Kh, const bf16* Kl,
                                               const bf16* Vh, const bf16* Vl,
                                               int kt, int tid)
{
    #pragma unroll
    for (int i = 0; i < 2; i++) {
        const int c  = i * 256 + tid;
        const int r  = c >> 3;
        const int d8 = c & 7;
        const size_t gg = (size_t)(kt*64 + r) * DH + d8 * 8;
        const uint32_t off = r * 128 + ((d8 ^ (r & 7)) << 4);
        cp16(uS + off,         &Kh[gg]);
        cp16(uS + 8192 + off,  &Kl[gg]);
        cp16(uS + 16384 + off, &Vh[gg]);
        cp16(uS + 24576 + off, &Vl[gg]);
    }
}

__global__ __launch_bounds__(256) void attn3_kernel()
{
    extern __shared__ char smx[];
    const uint32_t uB = smem_u32(smx);

    // longest-first: big q-tiles scheduled first
    const int qtb = (TT/128 - 1) - (blockIdx.x >> 6);
    const int bh  = blockIdx.x & 63;
    const int qb  = qtb * 128;
    const int tid = threadIdx.x;
    const int wid = tid >> 5;
    const int lane = tid & 31;

    const bf16* Qh = (const bf16*)g_Qh4 + (size_t)bh * TT * DH;
    const bf16* Ql = (const bf16*)g_Ql4 + (size_t)bh * TT * DH;
    const bf16* Kh = (const bf16*)g_Kh4 + (size_t)bh * TT * DH;
    const bf16* Kl = (const bf16*)g_Kl4 + (size_t)bh * TT * DH;
    const bf16* Vh = (const bf16*)g_Vh4 + (size_t)bh * TT * DH;
    const bf16* Vl = (const bf16*)g_Vl4 + (size_t)bh * TT * DH;

    // ---- stage Q tile (pure copy, swizzled; uses stage-0/1 region) ----
    #pragma unroll
    for (int i = 0; i < 4; i++) {
        const int c  = i * 256 + tid;
        const int m  = c >> 3;
        const int d8 = c & 7;
        const size_t g = (size_t)(qb + m) * DH + d8 * 8;
        const uint32_t off = m * 128 + ((d8 ^ (m & 7)) << 4);
        *(uint4*)(smx + off)         = *(const uint4*)&Qh[g];
        *(uint4*)(smx + 16384 + off) = *(const uint4*)&Ql[g];
    }
    __syncthreads();

    uint32_t qh[4][4], ql[4][4];
    {
        const int m = wid * 16 + (lane & 15);
        #pragma unroll
        for (int ks = 0; ks < 4; ks++) {
            const int k = ks * 16 + (lane >> 4) * 8;
            const uint32_t off = m * 128 + (((k >> 3) ^ (m & 7)) << 4);
            ldsm4(qh[ks][0], qh[ks][1], qh[ks][2], qh[ks][3], uB + off);
            ldsm4(ql[ks][0], ql[ks][1], ql[ks][2], ql[ks][3], uB + 16384 + off);
        }
    }
    __syncthreads();   // Q smem region free; stage 0 reuses it

    float oacc[8][4];
    #pragma unroll
    for (int nt = 0; nt < 8; nt++)
        #pragma unroll
        for (int r = 0; r < 4; r++) oacc[nt][r] = 0.f;
    float m0 = -1e30f, m1 = -1e30f, l0 = 0.f, l1 = 0.f;

    const int qw = qb + wid * 16;
    const int g  = lane >> 2;
    const int tg = lane & 3;
    const int row0 = qw + g;
    const float scale = 0.18033688011f;   // 0.125 * log2(e); softmax in base-2
    const int ktmax = 2 * qtb + 1;

    // prologue: stages 0,1 (ktmax >= 1 always)
    attn_load_tile(uB, Kh, Kl, Vh, Vl, 0, tid);
    cp_commit();
    attn_load_tile(uB + ATT_STAGE, Kh, Kl, Vh, Vl, 1, tid);
    cp_commit();

    int stage = 0;
    for (int kt = 0; kt <= ktmax; kt++) {
        cp_wait1();
        __syncthreads();
        if (kt + 2 <= ktmax) {
            int s2 = stage + 2; if (s2 >= 3) s2 -= 3;
            attn_load_tile(uB + s2 * ATT_STAGE, Kh, Kl, Vh, Vl, kt + 2, tid);
        }
        cp_commit();
        const uint32_t uS = uB + stage * ATT_STAGE;

        if (kt * 64 <= qw + 15) {
            // ---- S = Q K^T ----
            float sacc[8][4];
            #pragma unroll
            for (int nt = 0; nt < 8; nt++)
                #pragma unroll
                for (int r = 0; r < 4; r++) sacc[nt][r] = 0.f;

            #pragma unroll
            for (int ks = 0; ks < 4; ks++) {
                #pragma unroll
                for (int p = 0; p < 4; p++) {
                    const int n = p * 16 + (lane & 15);
                    const int k = ks * 16 + (lane >> 4) * 8;
                    const uint32_t off = n * 128 + (((k >> 3) ^ (n & 7)) << 4);
                    uint32_t b0a, b0b, b1a, b1b;
                    ldsm4(b0a, b0b, b1a, b1b, uS + off);          // Kh
                    mma16816(sacc[2*p  ], qh[ks][0], qh[ks][1], qh[ks][2], qh[ks][3], b0a, b1a);
                    mma16816(sacc[2*p+1], qh[ks][0], qh[ks][1], qh[ks][2], qh[ks][3], b0b, b1b);
                    mma16816(sacc[2*p  ], ql[ks][0], ql[ks][1], ql[ks][2], ql[ks][3], b0a, b1a);
                    mma16816(sacc[2*p+1], ql[ks][0], ql[ks][1], ql[ks][2], ql[ks][3], b0b, b1b);
                    ldsm4(b0a, b0b, b1a, b1b, uS + 8192 + off);   // Kl
                    mma16816(sacc[2*p  ], qh[ks][0], qh[ks][1], qh[ks][2], qh[ks][3], b0a, b1a);
                    mma16816(sacc[2*p+1], qh[ks][0], qh[ks][1], qh[ks][2], qh[ks][3], b0b, b1b);
                }
            }

            // ---- scale (base-2 domain) + causal mask ----
            if (kt * 64 + 63 > qw) {
                #pragma unroll
                for (int nt = 0; nt < 8; nt++) {
                    const int col = kt * 64 + nt * 8 + tg * 2;
                    sacc[nt][0] = (col     <= row0    ) ? sacc[nt][0] * scale : -1e30f;
                    sacc[nt][1] = (col + 1 <= row0    ) ? sacc[nt][1] * scale : -1e30f;
                    sacc[nt][2] = (col     <= row0 + 8) ? sacc[nt][2] * scale : -1e30f;
                    sacc[nt][3] = (col + 1 <= row0 + 8) ? sacc[nt][3] * scale : -1e30f;
                }
            } else {
                #pragma unroll
                for (int nt = 0; nt < 8; nt++)
                    #pragma unroll
                    for (int r = 0; r < 4; r++) sacc[nt][r] *= scale;
            }

            // ---- online softmax (base-2) ----
            float mx0 = -1e30f, mx1 = -1e30f;
            #pragma unroll
            for (int nt = 0; nt < 8; nt++) {
                mx0 = fmaxf(mx0, fmaxf(sacc[nt][0], sacc[nt][1]));
                mx1 = fmaxf(mx1, fmaxf(sacc[nt][2], sacc[nt][3]));
            }
            mx0 = fmaxf(mx0, __shfl_xor_sync(0xffffffffu, mx0, 1));
            mx0 = fmaxf(mx0, __shfl_xor_sync(0xffffffffu, mx0, 2));
            mx1 = fmaxf(mx1, __shfl_xor_sync(0xffffffffu, mx1, 1));
            mx1 = fmaxf(mx1, __shfl_xor_sync(0xffffffffu, mx1, 2));
            const float mn0 = fmaxf(m0, mx0);
            const float mn1 = fmaxf(m1, mx1);
            const float corr0 = exp2f(m0 - mn0);
            const float corr1 = exp2f(m1 - mn1);

            uint32_t ph01[8], ph23[8], pl01[8], pl23[8];
            float ps0 = 0.f, ps1 = 0.f;
            #pragma unroll
            for (int nt = 0; nt < 8; nt++) {
                const float p0 = exp2f(sacc[nt][0] - mn0);
                const float p1 = exp2f(sacc[nt][1] - mn0);
                const float p2 = exp2f(sacc[nt][2] - mn1);
                const float p3 = exp2f(sacc[nt][3] - mn1);
                ps0 += p0 + p1;
                ps1 += p2 + p3;
                split2(p0, p1, ph01[nt], pl01[nt]);
                split2(p2, p3, ph23[nt], pl23[nt]);
            }
            ps0 += __shfl_xor_sync(0xffffffffu, ps0, 1);
            ps0 += __shfl_xor_sync(0xffffffffu, ps0, 2);
            ps1 += __shfl_xor_sync(0xffffffffu, ps1, 1);
            ps1 += __shfl_xor_sync(0xffffffffu, ps1, 2);
            l0 = l0 * corr0 + ps0;  m0 = mn0;
            l1 = l1 * corr1 + ps1;  m1 = mn1;
            #pragma unroll
            for (int nt = 0; nt < 8; nt++) {
                oacc[nt][0] *= corr0; oacc[nt][1] *= corr0;
                oacc[nt][2] *= corr1; oacc[nt][3] *= corr1;
            }

            // ---- O += P V ----
            #pragma unroll
            for (int kk = 0; kk < 4; kk++) {
                const uint32_t a0 = ph01[2*kk],   a1 = ph23[2*kk];
                const uint32_t a2 = ph01[2*kk+1], a3 = ph23[2*kk+1];
                const uint32_t c0 = pl01[2*kk],   c1 = pl23[2*kk];
                const uint32_t c2 = pl01[2*kk+1], c3 = pl23[2*kk+1];
                #pragma unroll
                for (int dp = 0; dp < 4; dp++) {
                    const int r = kk * 16 + (lane & 15);
                    const int d = dp * 16 + (lane >> 4) * 8;
                    const uint32_t off = r * 128 + (((d >> 3) ^ (r & 7)) << 4);
                    uint32_t b0a, b1a, b0b, b1b;
                    ldsm4t(b0a, b1a, b0b, b1b, uS + 16384 + off);   // Vh
                    mma16816(oacc[2*dp  ], a0, a1, a2, a3, b0a, b1a);
                    mma16816(oacc[2*dp+1], a0, a1, a2, a3, b0b, b1b);
                    mma16816(oacc[2*dp  ], c0, c1, c2, c3, b0a, b1a);
                    mma16816(oacc[2*dp+1], c0, c1, c2, c3, b0b, b1b);
                    ldsm4t(b0a, b1a, b0b, b1b, uS + 24576 + off);   // Vl
                    mma16816(oacc[2*dp  ], a0, a1, a2, a3, b0a, b1a);
                    mma16816(oacc[2*dp+1], a0, a1, a2, a3, b0b, b1b);
                }
            }
        }
        stage++; if (stage == 3) stage = 0;
    }

    // ---- epilogue: normalize, split, write Y hi/lo planes [B,T,C] ----
    bf16* Yh = (bf16*)g_Yh4;
    bf16* Yl = (bf16*)g_Yl4;
    const float inv0 = 1.0f / l0;
    const float inv1 = 1.0f / l1;
    const int b = bh >> 4, h = bh & 15;
    #pragma unroll
    for (int nt = 0; nt < 8; nt++) {
        const int coln = h * 64 + nt * 8 + tg * 2;
        uint32_t hp, lp;
        split2(oacc[nt][0] * inv0, oacc[nt][1] * inv0, hp, lp);
        *(uint32_t*)&Yh[((size_t)(b*TT + row0))*CC + coln] = hp;
        *(uint32_t*)&Yl[((size_t)(b*TT + row0))*CC + coln] = lp;
        split2(oacc[nt][2] * inv1, oacc[nt][3] * inv1, hp, lp);
        *(uint32_t*)&Yh[((size_t)(b*TT + row0 + 8))*CC + coln] = hp;
        *(uint32_t*)&Yl[((size_t)(b*TT + row0 + 8))*CC + coln] = lp;
    }
}

// ---------------------------------------------------------------------------
extern "C" void kernel_launch(void* const* d_in, const int* in_sizes, int n_in,
                              void* d_out, int out_size)
{
    const float* x      = (const float*)d_in[0];
    const float* b_attn = (const float*)d_in[2];
    const float* b_proj = (const float*)d_in[4];
    float* out = (float*)d_out;

    static bool attr_set = false;
    if (!attr_set) {
        cudaFuncSetAttribute(attn3_kernel,
                             cudaFuncAttributeMaxDynamicSharedMemorySize, ATT_SMEM);
        cudaFuncSetAttribute(hgemm_kernel<0>,
                             cudaFuncAttributeMaxDynamicSharedMemorySize, GEMM_SMEM);
        cudaFuncSetAttribute(hgemm_kernel<1>,
                             cudaFuncAttributeMaxDynamicSharedMemorySize, GEMM_SMEM);
        attr_set = true;
    }

    // 0) one-time fp32 -> bf16 hi/lo split of x and weights
    convert_kernel<<<1024, 256>>>(x, (const float*)d_in[1], (const float*)d_in[3]);
    // 1) QKV GEMM (3-stage pipeline, 16 warps) + split-scatter into Q/K/V planes
    hgemm_kernel<0><<<dim3(3*CC/128, MM/128), 512, GEMM_SMEM>>>(b_attn, nullptr, 3*CC);
    // 2) Causal flash attention (3-stage pipeline, longest-first)
    attn3_kernel<<<TT/128 * BB*HH, 256, ATT_SMEM>>>();
    // 3) Output projection (3-stage pipeline, 16 warps)
    hgemm_kernel<1><<<dim3(CC/128, MM/128), 512, GEMM_SMEM>>>(b_proj, out, CC);
}